// round 1
// baseline (speedup 1.0000x reference)
#include <cuda_runtime.h>
#include <math.h>

#define DMODEL 768
#define FFD    3072
#define NL     6
#define NH     12
#define DH     64
#define SEQ    512
#define BATCH  8
#define NTOK   (BATCH*SEQ)   // 4096

// ---------------- scratch (static device globals; no runtime allocation) ----
__device__ float g_h  [NTOK*DMODEL];
__device__ float g_h2 [NTOK*DMODEL];
__device__ float g_q  [NTOK*DMODEL];
__device__ float g_k  [NTOK*DMODEL];
__device__ float g_v  [NTOK*DMODEL];
__device__ float g_ctx[NTOK*DMODEL];
__device__ float g_tmp[NTOK*DMODEL];
__device__ float g_ff [NTOK*FFD];

// ---------------- SGEMM: C = act((A[M,K] @ W[K,N] + bias[N]) * scale) -------
// 128x128 block tile, BK=8, 256 threads, 8x8 per-thread microtile.
#define BM 128
#define BN 128
#define BK 8
__global__ __launch_bounds__(256)
void sgemm_bias_act(const float* __restrict__ A, const float* __restrict__ W,
                    const float* __restrict__ bias, float* __restrict__ C,
                    int M, int N, int K, float scale, int act)
{
    __shared__ float As[BK][BM];   // A transposed: [k][m]
    __shared__ float Ws[BK][BN];   // [k][n]

    const int tid = threadIdx.x;
    const int tx  = tid & 15;      // 0..15 -> col group
    const int ty  = tid >> 4;      // 0..15 -> row group
    const int row0 = blockIdx.y * BM;
    const int col0 = blockIdx.x * BN;

    float acc[8][8];
    #pragma unroll
    for (int i = 0; i < 8; i++)
        #pragma unroll
        for (int j = 0; j < 8; j++) acc[i][j] = 0.f;

    const int aRow = tid >> 1;           // 0..127
    const int aCol = (tid & 1) * 4;      // 0 or 4
    const int wRow = tid >> 5;           // 0..7
    const int wCol = (tid & 31) * 4;     // 0..124

    const float* Aptr = A + (size_t)(row0 + aRow) * K + aCol;
    const float* Wptr = W + (size_t)wRow * N + col0 + wCol;

    for (int k0 = 0; k0 < K; k0 += BK) {
        float4 av = *(const float4*)(Aptr + k0);
        As[aCol + 0][aRow] = av.x;
        As[aCol + 1][aRow] = av.y;
        As[aCol + 2][aRow] = av.z;
        As[aCol + 3][aRow] = av.w;
        float4 wv = *(const float4*)(Wptr + (size_t)k0 * N);
        *(float4*)&Ws[wRow][wCol] = wv;
        __syncthreads();

        #pragma unroll
        for (int k = 0; k < BK; k++) {
            float a[8], b[8];
            #pragma unroll
            for (int i = 0; i < 8; i++) a[i] = As[k][ty * 8 + i];
            #pragma unroll
            for (int j = 0; j < 8; j++) b[j] = Ws[k][tx * 8 + j];
            #pragma unroll
            for (int i = 0; i < 8; i++)
                #pragma unroll
                for (int j = 0; j < 8; j++)
                    acc[i][j] += a[i] * b[j];
        }
        __syncthreads();
    }

    #pragma unroll
    for (int i = 0; i < 8; i++) {
        const int r = row0 + ty * 8 + i;
        #pragma unroll
        for (int j = 0; j < 8; j++) {
            const int c = col0 + tx * 8 + j;
            float v = (acc[i][j] + bias[c]) * scale;
            if (act) v = 0.5f * v * (1.f + erff(v * 0.70710678118654752f)); // exact GELU
            C[(size_t)r * N + c] = v;
        }
    }
}

// ---------------- fused attention (flash-style, fp32) -----------------------
// grid: (SEQ/32, NH, BATCH), 256 threads. q-tile 32 rows, k-tile 64 cols.
#define QT 32
#define KT 64
__global__ __launch_bounds__(256)
void attn_kernel(const float* __restrict__ Q, const float* __restrict__ K,
                 const float* __restrict__ V, const int* __restrict__ mask,
                 float* __restrict__ O)
{
    __shared__ float qs[QT][DH];        // 8 KB
    __shared__ float kv[KT][DH + 1];    // 16.25 KB (padded)
    __shared__ float sp[QT][KT + 1];    // 8.125 KB (padded)
    __shared__ float mrow[QT], lrow[QT], arow[QT];
    __shared__ float msk[KT];

    const int qt  = blockIdx.x;
    const int hh  = blockIdx.y;
    const int b   = blockIdx.z;
    const int tid = threadIdx.x;
    const int tx  = tid & 15;      // col group (4 cols)
    const int ty  = tid >> 4;      // row group (2 rows)
    const int r0  = ty * 2;
    const int c0  = tx * 4;

    const size_t base = (size_t)b * SEQ * DMODEL + (size_t)hh * DH;

    // load q tile (float4, coalesced)
    for (int l = tid; l < QT * DH / 4; l += 256) {
        int r  = l >> 4;
        int c4 = (l & 15) * 4;
        float4 v = *(const float4*)(Q + base + (size_t)(qt * QT + r) * DMODEL + c4);
        *(float4*)&qs[r][c4] = v;
    }
    if (tid < QT) { mrow[tid] = -1e30f; lrow[tid] = 0.f; }

    float acc[2][4];
    #pragma unroll
    for (int i = 0; i < 2; i++)
        #pragma unroll
        for (int j = 0; j < 4; j++) acc[i][j] = 0.f;

    for (int kt = 0; kt < SEQ / KT; kt++) {
        __syncthreads();
        // load K tile (scalar, coalesced) + mask
        for (int l = tid; l < KT * DH; l += 256) {
            int r = l >> 6, c = l & 63;
            kv[r][c] = K[base + (size_t)(kt * KT + r) * DMODEL + c];
        }
        if (tid < KT) msk[tid] = (float)mask[b * SEQ + kt * KT + tid];
        __syncthreads();

        // S = q @ k^T (q already scaled by 1/8 in projection)
        float s[2][4];
        #pragma unroll
        for (int i = 0; i < 2; i++)
            #pragma unroll
            for (int j = 0; j < 4; j++) s[i][j] = 0.f;
        #pragma unroll 4
        for (int d = 0; d < DH; d++) {
            float a0 = qs[r0][d], a1 = qs[r0 + 1][d];
            float bb[4];
            #pragma unroll
            for (int j = 0; j < 4; j++) bb[j] = kv[c0 + j][d];
            #pragma unroll
            for (int j = 0; j < 4; j++) {
                s[0][j] += a0 * bb[j];
                s[1][j] += a1 * bb[j];
            }
        }
        #pragma unroll
        for (int i = 0; i < 2; i++)
            #pragma unroll
            for (int j = 0; j < 4; j++) {
                int c = c0 + j;
                sp[r0 + i][c] = (msk[c] == 0.f) ? -1e9f : s[i][j];
            }
        __syncthreads();

        // load V tile (overwrites kv) while tid<QT does softmax bookkeeping
        for (int l = tid; l < KT * DH; l += 256) {
            int r = l >> 6, c = l & 63;
            kv[r][c] = V[base + (size_t)(kt * KT + r) * DMODEL + c];
        }
        if (tid < QT) {
            int row = tid;
            float mt = -1e30f;
            #pragma unroll 8
            for (int c = 0; c < KT; c++) mt = fmaxf(mt, sp[row][c]);
            float mo = mrow[row];
            float mn = fmaxf(mo, mt);
            float al = __expf(mo - mn);
            float sum = 0.f;
            #pragma unroll 8
            for (int c = 0; c < KT; c++) {
                float p = __expf(sp[row][c] - mn);
                sp[row][c] = p;
                sum += p;
            }
            lrow[row] = lrow[row] * al + sum;
            mrow[row] = mn;
            arow[row] = al;
        }
        __syncthreads();

        // acc = acc*alpha + P @ V
        float a0 = arow[r0], a1 = arow[r0 + 1];
        #pragma unroll
        for (int j = 0; j < 4; j++) { acc[0][j] *= a0; acc[1][j] *= a1; }
        #pragma unroll 4
        for (int k = 0; k < KT; k++) {
            float p0 = sp[r0][k], p1 = sp[r0 + 1][k];
            float vv[4];
            #pragma unroll
            for (int j = 0; j < 4; j++) vv[j] = kv[k][c0 + j];
            #pragma unroll
            for (int j = 0; j < 4; j++) {
                acc[0][j] += p0 * vv[j];
                acc[1][j] += p1 * vv[j];
            }
        }
    }
    __syncthreads();

    float inv0 = 1.f / lrow[r0], inv1 = 1.f / lrow[r0 + 1];
    #pragma unroll
    for (int j = 0; j < 4; j++) {
        O[base + (size_t)(qt * QT + r0)     * DMODEL + c0 + j] = acc[0][j] * inv0;
        O[base + (size_t)(qt * QT + r0 + 1) * DMODEL + c0 + j] = acc[1][j] * inv1;
    }
}

// ---------------- residual add + LayerNorm ----------------------------------
__device__ __forceinline__ float blockReduceSum(float val)
{
    __shared__ float red[8];
    __syncthreads();                       // safe reuse across calls
    int lane = threadIdx.x & 31, wid = threadIdx.x >> 5;
    #pragma unroll
    for (int o = 16; o > 0; o >>= 1) val += __shfl_down_sync(0xffffffffu, val, o);
    if (lane == 0) red[wid] = val;
    __syncthreads();
    if (wid == 0) {
        val = (lane < 8) ? red[lane] : 0.f;
        #pragma unroll
        for (int o = 4; o > 0; o >>= 1) val += __shfl_down_sync(0xffffffffu, val, o);
        if (lane == 0) red[0] = val;
    }
    __syncthreads();
    return red[0];
}

__global__ __launch_bounds__(256)
void add_ln_kernel(const float* __restrict__ a, const float* __restrict__ res,
                   const float* __restrict__ g, const float* __restrict__ bt,
                   float* __restrict__ out)
{
    const int row = blockIdx.x;
    const int tid = threadIdx.x;
    float v[3];
    float s = 0.f;
    #pragma unroll
    for (int i = 0; i < 3; i++) {
        int c = tid + i * 256;
        v[i] = a[(size_t)row * DMODEL + c] + res[(size_t)row * DMODEL + c];
        s += v[i];
    }
    s = blockReduceSum(s);
    const float mu = s * (1.f / DMODEL);
    float s2 = 0.f;
    #pragma unroll
    for (int i = 0; i < 3; i++) { float d = v[i] - mu; s2 += d * d; }
    s2 = blockReduceSum(s2);
    const float rs = rsqrtf(s2 * (1.f / DMODEL) + 1e-12f);
    #pragma unroll
    for (int i = 0; i < 3; i++) {
        int c = tid + i * 256;
        out[(size_t)row * DMODEL + c] = (v[i] - mu) * rs * g[c] + bt[c];
    }
}

// ---------------- driver -----------------------------------------------------
extern "C" void kernel_launch(void* const* d_in, const int* in_sizes, int n_in,
                              void* d_out, int out_size)
{
    const float* x     = (const float*)d_in[0];
    const int*   amask = (const int*)  d_in[1];
    const float* Wq    = (const float*)d_in[2];
    const float* bq    = (const float*)d_in[3];
    const float* Wk    = (const float*)d_in[4];
    const float* bk    = (const float*)d_in[5];
    const float* Wv    = (const float*)d_in[6];
    const float* bv    = (const float*)d_in[7];
    const float* Wo    = (const float*)d_in[8];
    const float* bo    = (const float*)d_in[9];
    const float* ln1g  = (const float*)d_in[10];
    const float* ln1b  = (const float*)d_in[11];
    const float* W1    = (const float*)d_in[12];
    const float* b1    = (const float*)d_in[13];
    const float* W2    = (const float*)d_in[14];
    const float* b2    = (const float*)d_in[15];
    const float* ln2g  = (const float*)d_in[16];
    const float* ln2b  = (const float*)d_in[17];
    float* out = (float*)d_out;

    float *h, *h2, *q, *k, *v, *ctx, *tmp, *ff;
    cudaGetSymbolAddress((void**)&h,   g_h);
    cudaGetSymbolAddress((void**)&h2,  g_h2);
    cudaGetSymbolAddress((void**)&q,   g_q);
    cudaGetSymbolAddress((void**)&k,   g_k);
    cudaGetSymbolAddress((void**)&v,   g_v);
    cudaGetSymbolAddress((void**)&ctx, g_ctx);
    cudaGetSymbolAddress((void**)&tmp, g_tmp);
    cudaGetSymbolAddress((void**)&ff,  g_ff);

    const dim3 gD(DMODEL / BN, NTOK / BM);     // N=768 GEMMs
    const dim3 gF(FFD    / BN, NTOK / BM);     // N=3072 GEMM
    const dim3 gA(SEQ / QT, NH, BATCH);

    for (int i = 0; i < NL; i++) {
        const float* cur = (i == 0) ? x : h;
        const size_t wdd = (size_t)i * DMODEL * DMODEL;
        const size_t wdf = (size_t)i * DMODEL * FFD;

        sgemm_bias_act<<<gD, 256>>>(cur, Wq + wdd, bq + i * DMODEL, q,
                                    NTOK, DMODEL, DMODEL, 0.125f, 0);
        sgemm_bias_act<<<gD, 256>>>(cur, Wk + wdd, bk + i * DMODEL, k,
                                    NTOK, DMODEL, DMODEL, 1.f, 0);
        sgemm_bias_act<<<gD, 256>>>(cur, Wv + wdd, bv + i * DMODEL, v,
                                    NTOK, DMODEL, DMODEL, 1.f, 0);
        attn_kernel<<<gA, 256>>>(q, k, v, amask, ctx);
        sgemm_bias_act<<<gD, 256>>>(ctx, Wo + wdd, bo + i * DMODEL, tmp,
                                    NTOK, DMODEL, DMODEL, 1.f, 0);
        add_ln_kernel<<<NTOK, 256>>>(tmp, cur, ln1g + i * DMODEL, ln1b + i * DMODEL, h2);
        sgemm_bias_act<<<gF, 256>>>(h2, W1 + wdf, b1 + i * FFD, ff,
                                    NTOK, FFD, DMODEL, 1.f, 1);
        sgemm_bias_act<<<gD, 256>>>(ff, W2 + wdf, b2 + i * DMODEL, tmp,
                                    NTOK, DMODEL, FFD, 1.f, 0);
        float* dst = (i == NL - 1) ? out : h;
        add_ln_kernel<<<NTOK, 256>>>(tmp, h2, ln2g + i * DMODEL, ln2b + i * DMODEL, dst);
    }
}

// round 3
// speedup vs baseline: 1.7138x; 1.7138x over previous
#include <cuda_runtime.h>
#include <cuda_bf16.h>
#include <math.h>
#include <stdint.h>

#define DMODEL 768
#define FFD    3072
#define NL     6
#define NH     12
#define DH     64
#define SEQ    512
#define BATCH  8
#define NTOK   (BATCH*SEQ)   // 4096

// ---------------- scratch (static device globals; no runtime allocation) ----
__device__ float g_h  [NTOK*DMODEL];
__device__ float g_h2 [NTOK*DMODEL];
__device__ float g_q  [NTOK*DMODEL];
__device__ float g_k  [NTOK*DMODEL];
__device__ float g_v  [NTOK*DMODEL];
__device__ float g_ctx[NTOK*DMODEL];
__device__ float g_tmp[NTOK*DMODEL];
__device__ float g_ff [NTOK*FFD];

// ================= helpers ==================================================
__device__ __forceinline__ uint32_t smem_u32(const void* p) {
    uint32_t a;
    asm("{ .reg .u64 t; cvta.to.shared.u64 t, %1; cvt.u32.u64 %0, t; }"
        : "=r"(a) : "l"(p));
    return a;
}

__device__ __forceinline__ uint32_t packbf(float x, float y) {
    __nv_bfloat162 t = __floats2bfloat162_rn(x, y);
    return *(uint32_t*)&t;
}

__device__ __forceinline__ void ldsm4(uint32_t* r, uint32_t addr) {
    asm volatile("ldmatrix.sync.aligned.m8n8.x4.shared.b16 {%0,%1,%2,%3}, [%4];"
                 : "=r"(r[0]), "=r"(r[1]), "=r"(r[2]), "=r"(r[3]) : "r"(addr));
}
__device__ __forceinline__ void ldsm4t(uint32_t* r, uint32_t addr) {
    asm volatile("ldmatrix.sync.aligned.m8n8.x4.trans.shared.b16 {%0,%1,%2,%3}, [%4];"
                 : "=r"(r[0]), "=r"(r[1]), "=r"(r[2]), "=r"(r[3]) : "r"(addr));
}
__device__ __forceinline__ void mma16816(float* d, const uint32_t* a,
                                         uint32_t b0, uint32_t b1) {
    asm volatile(
        "mma.sync.aligned.m16n8k16.row.col.f32.bf16.bf16.f32 "
        "{%0,%1,%2,%3}, {%4,%5,%6,%7}, {%8,%9}, {%0,%1,%2,%3};"
        : "+f"(d[0]), "+f"(d[1]), "+f"(d[2]), "+f"(d[3])
        : "r"(a[0]), "r"(a[1]), "r"(a[2]), "r"(a[3]), "r"(b0), "r"(b1));
}

// ================= split-bf16 HMMA GEMM =====================================
// C[M,N] = act((A[M,K] @ W[K,N] + bias)*scale), fp32 in/out.
// 128x128 CTA tile, BK=32, 8 warps (warp tile 32m x 64n), 3-term bf16 split.
// smem: Ahi/Alo [128][32] bf16, rows padded to 80B; Bhi/Blo [32][128] bf16,
// 256B rows, 16B-unit XOR swizzle by (k&7).
#define AHI 0
#define ALO 10240
#define BHI 20480
#define BLO 28672
#define GSMEM 36864

__global__ __launch_bounds__(256, 1)
void hmma_gemm(const float* __restrict__ A, const float* __restrict__ W,
               const float* __restrict__ bias, float* __restrict__ C,
               int M, int N, int K, float scale, int act)
{
    __shared__ __align__(16) char smem_raw[GSMEM];
    const uint32_t sb = smem_u32(smem_raw);

    const int tid = threadIdx.x;
    const int wid = tid >> 5;
    const int L   = tid & 31;
    const int wm  = wid & 3;          // 4 m-groups of 32 rows
    const int wn  = wid >> 2;         // 2 n-groups of 64 cols
    const int row0 = blockIdx.y * 128;
    const int col0 = blockIdx.x * 128;

    float acc[2][8][4];
    #pragma unroll
    for (int i = 0; i < 2; i++)
        #pragma unroll
        for (int j = 0; j < 8; j++)
            #pragma unroll
            for (int t = 0; t < 4; t++) acc[i][j][t] = 0.f;

    // global pointers (per-thread fixed lanes)
    const float* aptr = A + (size_t)(row0 + (tid >> 1)) * K + (tid & 1) * 16;
    const float* bptr = W + (size_t)(tid >> 3) * N + col0 + (tid & 7) * 16;

    // smem store offsets (bytes)
    const uint32_t aStOff = (uint32_t)((tid >> 1) * 80 + (tid & 1) * 32);
    const int bkk  = tid >> 3;            // 0..31 (k row)
    const int bu0  = (tid & 7) * 2;       // first 16B unit index
    const uint32_t bSt0 = (uint32_t)(bkk * 256 + ((bu0 ^ (bkk & 7)) << 4));
    const uint32_t bSt1 = (uint32_t)(bkk * 256 + (((bu0 + 1) ^ (bkk & 7)) << 4));

    // ldmatrix lane address components
    const uint32_t aLane = (uint32_t)((wm * 32 + (L & 15)) * 80 + ((L >> 4) << 4));
    const uint32_t bRow  = (uint32_t)(L & 15);
    const uint32_t bSwzX = (uint32_t)(L & 7);
    const uint32_t bUL   = (uint32_t)(wn * 8 + (L >> 4));   // + nj, then ^ swz

    const int KB = K >> 5;   // BK = 32

    float4 pa[4], pb[4];
    #pragma unroll
    for (int i = 0; i < 4; i++) {
        pa[i] = *(const float4*)(aptr + i * 4);
        pb[i] = *(const float4*)(bptr + i * 4);
    }

    for (int kb = 0; kb < KB; kb++) {
        // ---- convert + store A (hi/lo) ----
        {
            float f[16];
            #pragma unroll
            for (int i = 0; i < 4; i++) {
                f[i*4+0] = pa[i].x; f[i*4+1] = pa[i].y;
                f[i*4+2] = pa[i].z; f[i*4+3] = pa[i].w;
            }
            float hi[16];
            #pragma unroll
            for (int i = 0; i < 16; i++)
                hi[i] = __bfloat162float(__float2bfloat16_rn(f[i]));
            uint4 h0 = { packbf(hi[0],hi[1]), packbf(hi[2],hi[3]),
                         packbf(hi[4],hi[5]), packbf(hi[6],hi[7]) };
            uint4 h1 = { packbf(hi[8],hi[9]), packbf(hi[10],hi[11]),
                         packbf(hi[12],hi[13]), packbf(hi[14],hi[15]) };
            *(uint4*)(smem_raw + AHI + aStOff)      = h0;
            *(uint4*)(smem_raw + AHI + aStOff + 16) = h1;
            uint4 l0 = { packbf(f[0]-hi[0],   f[1]-hi[1]),
                         packbf(f[2]-hi[2],   f[3]-hi[3]),
                         packbf(f[4]-hi[4],   f[5]-hi[5]),
                         packbf(f[6]-hi[6],   f[7]-hi[7]) };
            uint4 l1 = { packbf(f[8]-hi[8],   f[9]-hi[9]),
                         packbf(f[10]-hi[10], f[11]-hi[11]),
                         packbf(f[12]-hi[12], f[13]-hi[13]),
                         packbf(f[14]-hi[14], f[15]-hi[15]) };
            *(uint4*)(smem_raw + ALO + aStOff)      = l0;
            *(uint4*)(smem_raw + ALO + aStOff + 16) = l1;
        }
        // ---- convert + store B (hi/lo) ----
        {
            float f[16];
            #pragma unroll
            for (int i = 0; i < 4; i++) {
                f[i*4+0] = pb[i].x; f[i*4+1] = pb[i].y;
                f[i*4+2] = pb[i].z; f[i*4+3] = pb[i].w;
            }
            float hi[16];
            #pragma unroll
            for (int i = 0; i < 16; i++)
                hi[i] = __bfloat162float(__float2bfloat16_rn(f[i]));
            uint4 h0 = { packbf(hi[0],hi[1]), packbf(hi[2],hi[3]),
                         packbf(hi[4],hi[5]), packbf(hi[6],hi[7]) };
            uint4 h1 = { packbf(hi[8],hi[9]), packbf(hi[10],hi[11]),
                         packbf(hi[12],hi[13]), packbf(hi[14],hi[15]) };
            *(uint4*)(smem_raw + BHI + bSt0) = h0;
            *(uint4*)(smem_raw + BHI + bSt1) = h1;
            uint4 l0 = { packbf(f[0]-hi[0],   f[1]-hi[1]),
                         packbf(f[2]-hi[2],   f[3]-hi[3]),
                         packbf(f[4]-hi[4],   f[5]-hi[5]),
                         packbf(f[6]-hi[6],   f[7]-hi[7]) };
            uint4 l1 = { packbf(f[8]-hi[8],   f[9]-hi[9]),
                         packbf(f[10]-hi[10], f[11]-hi[11]),
                         packbf(f[12]-hi[12], f[13]-hi[13]),
                         packbf(f[14]-hi[14], f[15]-hi[15]) };
            *(uint4*)(smem_raw + BLO + bSt0) = l0;
            *(uint4*)(smem_raw + BLO + bSt1) = l1;
        }
        __syncthreads();

        // ---- prefetch next tile (overlaps MMA phase) ----
        if (kb + 1 < KB) {
            const float* ap = aptr + (kb + 1) * 32;
            const float* bp = bptr + (size_t)(kb + 1) * 32 * N;
            #pragma unroll
            for (int i = 0; i < 4; i++) {
                pa[i] = *(const float4*)(ap + i * 4);
                pb[i] = *(const float4*)(bp + i * 4);
            }
        }

        // ---- MMA phase: 2 k16-steps x 3 split terms ----
        #pragma unroll
        for (int ks = 0; ks < 2; ks++) {
            uint32_t ah[2][4], al[2][4];
            #pragma unroll
            for (int mt = 0; mt < 2; mt++) {
                uint32_t off = aLane + (uint32_t)(mt * 16 * 80 + ks * 32);
                ldsm4(ah[mt], sb + AHI + off);
                ldsm4(al[mt], sb + ALO + off);
            }
            #pragma unroll
            for (int nj = 0; nj < 8; nj += 2) {
                uint32_t bh[4], bl[4];
                uint32_t u0 = ((bUL + nj) ^ bSwzX) << 4;
                uint32_t ro = (uint32_t)(ks * 16) + bRow;
                uint32_t off = ro * 256 + u0;
                ldsm4t(bh, sb + BHI + off);
                ldsm4t(bl, sb + BLO + off);
                #pragma unroll
                for (int mt = 0; mt < 2; mt++) {
                    mma16816(acc[mt][nj],   ah[mt], bh[0], bh[1]);
                    mma16816(acc[mt][nj+1], ah[mt], bh[2], bh[3]);
                    mma16816(acc[mt][nj],   ah[mt], bl[0], bl[1]);
                    mma16816(acc[mt][nj+1], ah[mt], bl[2], bl[3]);
                    mma16816(acc[mt][nj],   al[mt], bh[0], bh[1]);
                    mma16816(acc[mt][nj+1], al[mt], bh[2], bh[3]);
                }
            }
        }
        __syncthreads();
    }

    // ---- epilogue: stage through smem for coalesced stores -----------------
    float* sOut = (float*)smem_raw;      // 128 x 68 fp32 = 34816 B
    const int gid = L >> 2, tig = L & 3;
    #pragma unroll
    for (int h = 0; h < 2; h++) {
        if (wn == h) {
            #pragma unroll
            for (int mt = 0; mt < 2; mt++) {
                #pragma unroll
                for (int nt = 0; nt < 8; nt++) {
                    const int srow = wm * 32 + mt * 16 + gid;
                    const int scol = nt * 8 + tig * 2;
                    const int gc   = col0 + h * 64 + scol;
                    float b0v = bias[gc], b1v = bias[gc + 1];
                    float v0 = (acc[mt][nt][0] + b0v) * scale;
                    float v1 = (acc[mt][nt][1] + b1v) * scale;
                    float v2 = (acc[mt][nt][2] + b0v) * scale;
                    float v3 = (acc[mt][nt][3] + b1v) * scale;
                    if (act) {
                        v0 = 0.5f*v0*(1.f+erff(v0*0.70710678118654752f));
                        v1 = 0.5f*v1*(1.f+erff(v1*0.70710678118654752f));
                        v2 = 0.5f*v2*(1.f+erff(v2*0.70710678118654752f));
                        v3 = 0.5f*v3*(1.f+erff(v3*0.70710678118654752f));
                    }
                    sOut[srow * 68 + scol]       = v0;
                    sOut[srow * 68 + scol + 1]   = v1;
                    sOut[(srow+8) * 68 + scol]   = v2;
                    sOut[(srow+8) * 68 + scol+1] = v3;
                }
            }
        }
        __syncthreads();
        #pragma unroll
        for (int i = 0; i < 8; i++) {
            const int f   = tid + i * 256;
            const int row = f >> 4;
            const int c4  = (f & 15) * 4;
            float4 v = *(const float4*)(sOut + row * 68 + c4);
            *(float4*)(C + (size_t)(row0 + row) * N + col0 + h * 64 + c4) = v;
        }
        __syncthreads();
    }
}

// ---------------- fused attention (flash-style, fp32) -----------------------
#define QT 32
#define KT 64
__global__ __launch_bounds__(256)
void attn_kernel(const float* __restrict__ Q, const float* __restrict__ K,
                 const float* __restrict__ V, const int* __restrict__ mask,
                 float* __restrict__ O)
{
    __shared__ float qs[QT][DH];
    __shared__ float kv[KT][DH + 1];
    __shared__ float sp[QT][KT + 1];
    __shared__ float mrow[QT], lrow[QT], arow[QT];
    __shared__ float msk[KT];

    const int qt  = blockIdx.x;
    const int hh  = blockIdx.y;
    const int b   = blockIdx.z;
    const int tid = threadIdx.x;
    const int tx  = tid & 15;
    const int ty  = tid >> 4;
    const int r0  = ty * 2;
    const int c0  = tx * 4;

    const size_t base = (size_t)b * SEQ * DMODEL + (size_t)hh * DH;

    for (int l = tid; l < QT * DH / 4; l += 256) {
        int r  = l >> 4;
        int c4 = (l & 15) * 4;
        float4 v = *(const float4*)(Q + base + (size_t)(qt * QT + r) * DMODEL + c4);
        *(float4*)&qs[r][c4] = v;
    }
    if (tid < QT) { mrow[tid] = -1e30f; lrow[tid] = 0.f; }

    float acc[2][4];
    #pragma unroll
    for (int i = 0; i < 2; i++)
        #pragma unroll
        for (int j = 0; j < 4; j++) acc[i][j] = 0.f;

    for (int kt = 0; kt < SEQ / KT; kt++) {
        __syncthreads();
        for (int l = tid; l < KT * DH; l += 256) {
            int r = l >> 6, c = l & 63;
            kv[r][c] = K[base + (size_t)(kt * KT + r) * DMODEL + c];
        }
        if (tid < KT) msk[tid] = (float)mask[b * SEQ + kt * KT + tid];
        __syncthreads();

        float s[2][4];
        #pragma unroll
        for (int i = 0; i < 2; i++)
            #pragma unroll
            for (int j = 0; j < 4; j++) s[i][j] = 0.f;
        #pragma unroll 4
        for (int d = 0; d < DH; d++) {
            float a0 = qs[r0][d], a1 = qs[r0 + 1][d];
            float bb[4];
            #pragma unroll
            for (int j = 0; j < 4; j++) bb[j] = kv[c0 + j][d];
            #pragma unroll
            for (int j = 0; j < 4; j++) {
                s[0][j] += a0 * bb[j];
                s[1][j] += a1 * bb[j];
            }
        }
        #pragma unroll
        for (int i = 0; i < 2; i++)
            #pragma unroll
            for (int j = 0; j < 4; j++) {
                int c = c0 + j;
                sp[r0 + i][c] = (msk[c] == 0.f) ? -1e9f : s[i][j];
            }
        __syncthreads();

        for (int l = tid; l < KT * DH; l += 256) {
            int r = l >> 6, c = l & 63;
            kv[r][c] = V[base + (size_t)(kt * KT + r) * DMODEL + c];
        }
        if (tid < QT) {
            int row = tid;
            float mt = -1e30f;
            #pragma unroll 8
            for (int c = 0; c < KT; c++) mt = fmaxf(mt, sp[row][c]);
            float mo = mrow[row];
            float mn = fmaxf(mo, mt);
            float al = __expf(mo - mn);
            float sum = 0.f;
            #pragma unroll 8
            for (int c = 0; c < KT; c++) {
                float p = __expf(sp[row][c] - mn);
                sp[row][c] = p;
                sum += p;
            }
            lrow[row] = lrow[row] * al + sum;
            mrow[row] = mn;
            arow[row] = al;
        }
        __syncthreads();

        float a0 = arow[r0], a1 = arow[r0 + 1];
        #pragma unroll
        for (int j = 0; j < 4; j++) { acc[0][j] *= a0; acc[1][j] *= a1; }
        #pragma unroll 4
        for (int k = 0; k < KT; k++) {
            float p0 = sp[r0][k], p1 = sp[r0 + 1][k];
            float vv[4];
            #pragma unroll
            for (int j = 0; j < 4; j++) vv[j] = kv[k][c0 + j];
            #pragma unroll
            for (int j = 0; j < 4; j++) {
                acc[0][j] += p0 * vv[j];
                acc[1][j] += p1 * vv[j];
            }
        }
    }
    __syncthreads();

    float inv0 = 1.f / lrow[r0], inv1 = 1.f / lrow[r0 + 1];
    #pragma unroll
    for (int j = 0; j < 4; j++) {
        O[base + (size_t)(qt * QT + r0)     * DMODEL + c0 + j] = acc[0][j] * inv0;
        O[base + (size_t)(qt * QT + r0 + 1) * DMODEL + c0 + j] = acc[1][j] * inv1;
    }
}

// ---------------- residual add + LayerNorm ----------------------------------
__device__ __forceinline__ float blockReduceSum(float val)
{
    __shared__ float red[8];
    __syncthreads();
    int lane = threadIdx.x & 31, wid = threadIdx.x >> 5;
    #pragma unroll
    for (int o = 16; o > 0; o >>= 1) val += __shfl_down_sync(0xffffffffu, val, o);
    if (lane == 0) red[wid] = val;
    __syncthreads();
    if (wid == 0) {
        val = (lane < 8) ? red[lane] : 0.f;
        #pragma unroll
        for (int o = 4; o > 0; o >>= 1) val += __shfl_down_sync(0xffffffffu, val, o);
        if (lane == 0) red[0] = val;
    }
    __syncthreads();
    return red[0];
}

__global__ __launch_bounds__(256)
void add_ln_kernel(const float* __restrict__ a, const float* __restrict__ res,
                   const float* __restrict__ g, const float* __restrict__ bt,
                   float* __restrict__ out)
{
    const int row = blockIdx.x;
    const int tid = threadIdx.x;
    float v[3];
    float s = 0.f;
    #pragma unroll
    for (int i = 0; i < 3; i++) {
        int c = tid + i * 256;
        v[i] = a[(size_t)row * DMODEL + c] + res[(size_t)row * DMODEL + c];
        s += v[i];
    }
    s = blockReduceSum(s);
    const float mu = s * (1.f / DMODEL);
    float s2 = 0.f;
    #pragma unroll
    for (int i = 0; i < 3; i++) { float d = v[i] - mu; s2 += d * d; }
    s2 = blockReduceSum(s2);
    const float rs = rsqrtf(s2 * (1.f / DMODEL) + 1e-12f);
    #pragma unroll
    for (int i = 0; i < 3; i++) {
        int c = tid + i * 256;
        out[(size_t)row * DMODEL + c] = (v[i] - mu) * rs * g[c] + bt[c];
    }
}

// ---------------- driver -----------------------------------------------------
extern "C" void kernel_launch(void* const* d_in, const int* in_sizes, int n_in,
                              void* d_out, int out_size)
{
    const float* x     = (const float*)d_in[0];
    const int*   amask = (const int*)  d_in[1];
    const float* Wq    = (const float*)d_in[2];
    const float* bq    = (const float*)d_in[3];
    const float* Wk    = (const float*)d_in[4];
    const float* bk    = (const float*)d_in[5];
    const float* Wv    = (const float*)d_in[6];
    const float* bv    = (const float*)d_in[7];
    const float* Wo    = (const float*)d_in[8];
    const float* bo    = (const float*)d_in[9];
    const float* ln1g  = (const float*)d_in[10];
    const float* ln1b  = (const float*)d_in[11];
    const float* W1    = (const float*)d_in[12];
    const float* b1    = (const float*)d_in[13];
    const float* W2    = (const float*)d_in[14];
    const float* b2    = (const float*)d_in[15];
    const float* ln2g  = (const float*)d_in[16];
    const float* ln2b  = (const float*)d_in[17];
    float* out = (float*)d_out;

    float *h, *h2, *q, *k, *v, *ctx, *tmp, *ff;
    cudaGetSymbolAddress((void**)&h,   g_h);
    cudaGetSymbolAddress((void**)&h2,  g_h2);
    cudaGetSymbolAddress((void**)&q,   g_q);
    cudaGetSymbolAddress((void**)&k,   g_k);
    cudaGetSymbolAddress((void**)&v,   g_v);
    cudaGetSymbolAddress((void**)&ctx, g_ctx);
    cudaGetSymbolAddress((void**)&tmp, g_tmp);
    cudaGetSymbolAddress((void**)&ff,  g_ff);

    const dim3 gD(DMODEL / 128, NTOK / 128);   // (6, 32)
    const dim3 gF(FFD    / 128, NTOK / 128);   // (24, 32)
    const dim3 gA(SEQ / QT, NH, BATCH);

    for (int i = 0; i < NL; i++) {
        const float* cur = (i == 0) ? x : h;
        const size_t wdd = (size_t)i * DMODEL * DMODEL;
        const size_t wdf = (size_t)i * DMODEL * FFD;

        hmma_gemm<<<gD, 256>>>(cur, Wq + wdd, bq + i * DMODEL, q,
                               NTOK, DMODEL, DMODEL, 0.125f, 0);
        hmma_gemm<<<gD, 256>>>(cur, Wk + wdd, bk + i * DMODEL, k,
                               NTOK, DMODEL, DMODEL, 1.f, 0);
        hmma_gemm<<<gD, 256>>>(cur, Wv + wdd, bv + i * DMODEL, v,
                               NTOK, DMODEL, DMODEL, 1.f, 0);
        attn_kernel<<<gA, 256>>>(q, k, v, amask, ctx);
        hmma_gemm<<<gD, 256>>>(ctx, Wo + wdd, bo + i * DMODEL, tmp,
                               NTOK, DMODEL, DMODEL, 1.f, 0);
        add_ln_kernel<<<NTOK, 256>>>(tmp, cur, ln1g + i * DMODEL, ln1b + i * DMODEL, h2);
        hmma_gemm<<<gF, 256>>>(h2, W1 + wdf, b1 + i * FFD, ff,
                               NTOK, FFD, DMODEL, 1.f, 1);
        hmma_gemm<<<gD, 256>>>(ff, W2 + wdf, b2 + i * DMODEL, tmp,
                               NTOK, DMODEL, FFD, 1.f, 0);
        float* dst = (i == NL - 1) ? out : h;
        add_ln_kernel<<<NTOK, 256>>>(tmp, h2, ln2g + i * DMODEL, ln2b + i * DMODEL, dst);
    }
}

// round 4
// speedup vs baseline: 2.3683x; 1.3819x over previous
#include <cuda_runtime.h>
#include <cuda_bf16.h>
#include <math.h>
#include <stdint.h>

#define DMODEL 768
#define FFD    3072
#define NL     6
#define NH     12
#define DH     64
#define SEQ    512
#define BATCH  8
#define NTOK   (BATCH*SEQ)   // 4096

#define SZ_DD  (NL*DMODEL*DMODEL)      // 3538944
#define SZ_DF  (NL*DMODEL*FFD)         // 14155776
#define OQ 0
#define OKk (SZ_DD)
#define OV  (2*SZ_DD)
#define OO  (3*SZ_DD)
#define O1  (4*SZ_DD)
#define O2  (4*SZ_DD + SZ_DF)
#define WTOT (4*SZ_DD + 2*SZ_DF)       // 42467328

// ---------------- scratch (static device globals; no runtime allocation) ----
__device__ float g_h  [NTOK*DMODEL];
__device__ float g_h2 [NTOK*DMODEL];
__device__ float g_q  [NTOK*DMODEL];
__device__ float g_k  [NTOK*DMODEL];
__device__ float g_v  [NTOK*DMODEL];
__device__ float g_ctx[NTOK*DMODEL];
__device__ float g_tmp[NTOK*DMODEL];
__device__ float g_ff [NTOK*FFD];
__device__ __nv_bfloat16 g_whi[WTOT];
__device__ __nv_bfloat16 g_wlo[WTOT];
__device__ __nv_bfloat16 g_ahi[NTOK*DMODEL];
__device__ __nv_bfloat16 g_alo[NTOK*DMODEL];
__device__ __nv_bfloat16 g_fhi[NTOK*FFD];
__device__ __nv_bfloat16 g_flo[NTOK*FFD];

// ================= helpers ==================================================
__device__ __forceinline__ uint32_t smem_u32(const void* p) {
    uint32_t a;
    asm("{ .reg .u64 t; cvta.to.shared.u64 t, %1; cvt.u32.u64 %0, t; }"
        : "=r"(a) : "l"(p));
    return a;
}
__device__ __forceinline__ uint32_t packbf(float x, float y) {
    __nv_bfloat162 t = __floats2bfloat162_rn(x, y);
    return *(uint32_t*)&t;
}
__device__ __forceinline__ void cpa16(uint32_t dst, const void* src) {
    asm volatile("cp.async.cg.shared.global [%0], [%1], 16;"
                 :: "r"(dst), "l"(src) : "memory");
}
__device__ __forceinline__ void ldsm4(uint32_t* r, uint32_t addr) {
    asm volatile("ldmatrix.sync.aligned.m8n8.x4.shared.b16 {%0,%1,%2,%3}, [%4];"
                 : "=r"(r[0]), "=r"(r[1]), "=r"(r[2]), "=r"(r[3]) : "r"(addr));
}
__device__ __forceinline__ void ldsm4t(uint32_t* r, uint32_t addr) {
    asm volatile("ldmatrix.sync.aligned.m8n8.x4.trans.shared.b16 {%0,%1,%2,%3}, [%4];"
                 : "=r"(r[0]), "=r"(r[1]), "=r"(r[2]), "=r"(r[3]) : "r"(addr));
}
__device__ __forceinline__ void mma16816(float* d, const uint32_t* a,
                                         uint32_t b0, uint32_t b1) {
    asm volatile(
        "mma.sync.aligned.m16n8k16.row.col.f32.bf16.bf16.f32 "
        "{%0,%1,%2,%3}, {%4,%5,%6,%7}, {%8,%9}, {%0,%1,%2,%3};"
        : "+f"(d[0]), "+f"(d[1]), "+f"(d[2]), "+f"(d[3])
        : "r"(a[0]), "r"(a[1]), "r"(a[2]), "r"(a[3]), "r"(b0), "r"(b1));
}

// ================= fp32 -> bf16 hi/lo split conversion ======================
__global__ __launch_bounds__(256)
void f2bf(const float4* __restrict__ in, uint2* __restrict__ hi,
          uint2* __restrict__ lo, int n4)
{
    int i = blockIdx.x * 256 + threadIdx.x;
    if (i >= n4) return;
    float4 f = in[i];
    float hx = __bfloat162float(__float2bfloat16_rn(f.x));
    float hy = __bfloat162float(__float2bfloat16_rn(f.y));
    float hz = __bfloat162float(__float2bfloat16_rn(f.z));
    float hw = __bfloat162float(__float2bfloat16_rn(f.w));
    uint2 H = { packbf(hx, hy), packbf(hz, hw) };
    uint2 Lo = { packbf(f.x - hx, f.y - hy), packbf(f.z - hz, f.w - hw) };
    hi[i] = H;
    lo[i] = Lo;
}

// ================= split-bf16 HMMA GEMM (cp.async double-buffered) ==========
// stage layout (bytes): Ahi[0,10240) Alo[10240,20480) Bhi[20480,28672) Blo[28672,36864)
#define STG 36864
#define GEMM_SMEM (2*STG)

__global__ __launch_bounds__(256, 1)
void hmma_gemm(const __nv_bfloat16* __restrict__ Ahi, const __nv_bfloat16* __restrict__ Alo,
               const __nv_bfloat16* __restrict__ Bhi, const __nv_bfloat16* __restrict__ Blo,
               const float* __restrict__ bias, float* __restrict__ C,
               __nv_bfloat16* __restrict__ Chi, __nv_bfloat16* __restrict__ Clo,
               int M, int N, int K, float scale, int act)
{
    extern __shared__ char dsm[];
    const uint32_t sb = smem_u32(dsm);
    const int tid = threadIdx.x;
    const int wid = tid >> 5, L = tid & 31;
    const int wm = wid & 3, wn = wid >> 2;
    const int row0 = blockIdx.y * 128, col0 = blockIdx.x * 128;

    float acc[2][8][4];
    #pragma unroll
    for (int i = 0; i < 2; i++)
        #pragma unroll
        for (int j = 0; j < 8; j++)
            #pragma unroll
            for (int t = 0; t < 4; t++) acc[i][j][t] = 0.f;

    // per-thread load descriptors
    const int aR0 = tid >> 2, aU = tid & 3;      // A: 2 chunks/buffer (rows aR0, aR0+64)
    const int bR0 = tid >> 4, bU = tid & 15;     // B: 2 chunks/buffer (rows bR0, bR0+16)
    const uint32_t aDst0 = (uint32_t)(aR0 * 80 + aU * 16);
    const uint32_t bDst0 = (uint32_t)(bR0 * 256 + ((bU ^ (bR0 & 7)) << 4));

    const __nv_bfloat16* aHb = Ahi + (size_t)(row0 + aR0) * K + aU * 8;
    const __nv_bfloat16* aLb = Alo + (size_t)(row0 + aR0) * K + aU * 8;
    const __nv_bfloat16* bHb = Bhi + (size_t)bR0 * N + col0 + bU * 8;
    const __nv_bfloat16* bLb = Blo + (size_t)bR0 * N + col0 + bU * 8;

    const int KB = K >> 5;

    #define ISSUE(kb) do {                                                  \
        const uint32_t stg_ = sb + (uint32_t)((kb) & 1) * STG;              \
        const int k0_ = (kb) * 32;                                          \
        cpa16(stg_ + aDst0,              aHb + k0_);                        \
        cpa16(stg_ + aDst0 + 10240,      aLb + k0_);                        \
        cpa16(stg_ + aDst0 + 5120,       aHb + k0_ + (size_t)64 * K);       \
        cpa16(stg_ + aDst0 + 5120+10240, aLb + k0_ + (size_t)64 * K);       \
        cpa16(stg_ + 20480 + bDst0,        bHb + (size_t)k0_ * N);          \
        cpa16(stg_ + 28672 + bDst0,        bLb + (size_t)k0_ * N);          \
        cpa16(stg_ + 20480 + bDst0 + 4096, bHb + (size_t)(k0_ + 16) * N);   \
        cpa16(stg_ + 28672 + bDst0 + 4096, bLb + (size_t)(k0_ + 16) * N);   \
        asm volatile("cp.async.commit_group;" ::: "memory");                \
    } while (0)

    ISSUE(0);

    const uint32_t aLane = (uint32_t)((wm * 32 + (L & 15)) * 80 + ((L >> 4) << 4));
    const uint32_t bRow  = (uint32_t)(L & 15);
    const uint32_t bSwzX = (uint32_t)(L & 7);
    const uint32_t bUL   = (uint32_t)(wn * 8 + (L >> 4));

    for (int kb = 0; kb < KB; kb++) {
        const uint32_t stg = sb + (uint32_t)(kb & 1) * STG;
        asm volatile("cp.async.wait_group 0;" ::: "memory");
        __syncthreads();
        if (kb + 1 < KB) ISSUE(kb + 1);

        #pragma unroll
        for (int ks = 0; ks < 2; ks++) {
            uint32_t ah[2][4], al[2][4];
            #pragma unroll
            for (int mt = 0; mt < 2; mt++) {
                uint32_t off = aLane + (uint32_t)(mt * 16 * 80 + ks * 32);
                ldsm4(ah[mt], stg + off);
                ldsm4(al[mt], stg + 10240 + off);
            }
            #pragma unroll
            for (int nj = 0; nj < 8; nj += 2) {
                uint32_t bh[4], bl[4];
                uint32_t off = (uint32_t)(ks * 16 + bRow) * 256
                             + (((bUL + nj) ^ bSwzX) << 4);
                ldsm4t(bh, stg + 20480 + off);
                ldsm4t(bl, stg + 28672 + off);
                #pragma unroll
                for (int mt = 0; mt < 2; mt++) {
                    mma16816(acc[mt][nj],   ah[mt], bh[0], bh[1]);
                    mma16816(acc[mt][nj+1], ah[mt], bh[2], bh[3]);
                    mma16816(acc[mt][nj],   ah[mt], bl[0], bl[1]);
                    mma16816(acc[mt][nj+1], ah[mt], bl[2], bl[3]);
                    mma16816(acc[mt][nj],   al[mt], bh[0], bh[1]);
                    mma16816(acc[mt][nj+1], al[mt], bh[2], bh[3]);
                }
            }
        }
        __syncthreads();
    }
    #undef ISSUE

    // ---- epilogue: stage through smem for coalesced stores -----------------
    float* sOut = (float*)dsm;           // 128 x 68 fp32 = 34816 B (stage 0)
    const int gid = L >> 2, tig = L & 3;
    #pragma unroll
    for (int h = 0; h < 2; h++) {
        if (wn == h) {
            #pragma unroll
            for (int mt = 0; mt < 2; mt++) {
                #pragma unroll
                for (int nt = 0; nt < 8; nt++) {
                    const int srow = wm * 32 + mt * 16 + gid;
                    const int scol = nt * 8 + tig * 2;
                    const int gc   = col0 + h * 64 + scol;
                    float b0v = bias[gc], b1v = bias[gc + 1];
                    float v0 = (acc[mt][nt][0] + b0v) * scale;
                    float v1 = (acc[mt][nt][1] + b1v) * scale;
                    float v2 = (acc[mt][nt][2] + b0v) * scale;
                    float v3 = (acc[mt][nt][3] + b1v) * scale;
                    if (act) {
                        v0 = 0.5f*v0*(1.f+erff(v0*0.70710678118654752f));
                        v1 = 0.5f*v1*(1.f+erff(v1*0.70710678118654752f));
                        v2 = 0.5f*v2*(1.f+erff(v2*0.70710678118654752f));
                        v3 = 0.5f*v3*(1.f+erff(v3*0.70710678118654752f));
                    }
                    sOut[srow * 68 + scol]       = v0;
                    sOut[srow * 68 + scol + 1]   = v1;
                    sOut[(srow+8) * 68 + scol]   = v2;
                    sOut[(srow+8) * 68 + scol+1] = v3;
                }
            }
        }
        __syncthreads();
        #pragma unroll
        for (int i = 0; i < 8; i++) {
            const int f   = tid + i * 256;
            const int row = f >> 4;
            const int c4  = (f & 15) * 4;
            float4 v = *(const float4*)(sOut + row * 68 + c4);
            const size_t gidx = (size_t)(row0 + row) * N + col0 + h * 64 + c4;
            *(float4*)(C + gidx) = v;
            if (Chi) {
                float hx = __bfloat162float(__float2bfloat16_rn(v.x));
                float hy = __bfloat162float(__float2bfloat16_rn(v.y));
                float hz = __bfloat162float(__float2bfloat16_rn(v.z));
                float hw = __bfloat162float(__float2bfloat16_rn(v.w));
                uint2 H = { packbf(hx, hy), packbf(hz, hw) };
                uint2 Lo = { packbf(v.x - hx, v.y - hy), packbf(v.z - hz, v.w - hw) };
                *(uint2*)(Chi + gidx) = H;
                *(uint2*)(Clo + gidx) = Lo;
            }
        }
        __syncthreads();
    }
}

// ---------------- fused attention v2 (QT=64, 4x4 microtile) -----------------
// dyn smem floats: qs[64*64]@0  kv[64*65]@4096  sp[64*65]@8256  msk[64]@12416
#define ATT_SMEM (12480*4)
__global__ __launch_bounds__(256)
void attn_kernel(const float* __restrict__ Q, const float* __restrict__ K,
                 const float* __restrict__ V, const int* __restrict__ mask,
                 float* __restrict__ O)
{
    extern __shared__ float s[];
    float* qs  = s;
    float* kv  = s + 4096;
    float* sp  = s + 8256;
    float* msk = s + 12416;

    const int qt  = blockIdx.x;
    const int hh  = blockIdx.y;
    const int b   = blockIdx.z;
    const int tid = threadIdx.x;
    const int tx  = tid & 15;
    const int ty  = tid >> 4;
    const int r0  = ty * 4;

    const size_t base = (size_t)b * SEQ * DMODEL + (size_t)hh * DH;

    // load q tile 64x64 (float4)
    for (int l = tid; l < 1024; l += 256) {
        int r  = l >> 4;
        int c4 = (l & 15) * 4;
        float4 v = *(const float4*)(Q + base + (size_t)(qt * 64 + r) * DMODEL + c4);
        *(float4*)&qs[r * 64 + c4] = v;
    }

    float m_run[4], l_run[4], acc[4][4];
    #pragma unroll
    for (int i = 0; i < 4; i++) {
        m_run[i] = -1e30f; l_run[i] = 0.f;
        #pragma unroll
        for (int j = 0; j < 4; j++) acc[i][j] = 0.f;
    }

    for (int kt = 0; kt < SEQ / 64; kt++) {
        __syncthreads();                       // prior PV done with kv
        for (int l = tid; l < 4096; l += 256) {
            int r = l >> 6, c = l & 63;
            kv[r * 65 + c] = K[base + (size_t)(kt * 64 + r) * DMODEL + c];
        }
        if (tid < 64) msk[tid] = (float)mask[b * SEQ + kt * 64 + tid];
        __syncthreads();

        // S = q @ k^T
        float sc[4][4];
        #pragma unroll
        for (int i = 0; i < 4; i++)
            #pragma unroll
            for (int j = 0; j < 4; j++) sc[i][j] = 0.f;
        #pragma unroll 4
        for (int d = 0; d < DH; d++) {
            float qv[4];
            #pragma unroll
            for (int i = 0; i < 4; i++) qv[i] = qs[(r0 + i) * 64 + d];
            #pragma unroll
            for (int j = 0; j < 4; j++) {
                float kval = kv[(tx + 16 * j) * 65 + d];
                #pragma unroll
                for (int i = 0; i < 4; i++) sc[i][j] += qv[i] * kval;
            }
        }
        #pragma unroll
        for (int j = 0; j < 4; j++) {
            if (msk[tx + 16 * j] == 0.f) {
                #pragma unroll
                for (int i = 0; i < 4; i++) sc[i][j] = -1e9f;
            }
        }

        // online softmax, state register-resident per half-warp
        #pragma unroll
        for (int i = 0; i < 4; i++) {
            float mt = fmaxf(fmaxf(sc[i][0], sc[i][1]), fmaxf(sc[i][2], sc[i][3]));
            #pragma unroll
            for (int o = 8; o > 0; o >>= 1)
                mt = fmaxf(mt, __shfl_xor_sync(0xffffffffu, mt, o, 16));
            float mn = fmaxf(m_run[i], mt);
            float al = __expf(m_run[i] - mn);
            m_run[i] = mn;
            float ps = 0.f;
            #pragma unroll
            for (int j = 0; j < 4; j++) {
                float p = __expf(sc[i][j] - mn);
                ps += p;
                sp[(r0 + i) * 65 + tx + 16 * j] = p;
            }
            #pragma unroll
            for (int o = 8; o > 0; o >>= 1)
                ps += __shfl_xor_sync(0xffffffffu, ps, o, 16);
            l_run[i] = l_run[i] * al + ps;
            #pragma unroll
            for (int j = 0; j < 4; j++) acc[i][j] *= al;
        }
        __syncwarp();
        __syncthreads();                       // everyone done reading kv(K)
        for (int l = tid; l < 4096; l += 256) {
            int r = l >> 6, c = l & 63;
            kv[r * 65 + c] = V[base + (size_t)(kt * 64 + r) * DMODEL + c];
        }
        __syncthreads();

        // acc += P @ V
        #pragma unroll 4
        for (int k = 0; k < 64; k++) {
            float pv[4];
            #pragma unroll
            for (int i = 0; i < 4; i++) pv[i] = sp[(r0 + i) * 65 + k];
            #pragma unroll
            for (int j = 0; j < 4; j++) {
                float vval = kv[k * 65 + tx + 16 * j];
                #pragma unroll
                for (int i = 0; i < 4; i++) acc[i][j] += pv[i] * vval;
            }
        }
    }

    #pragma unroll
    for (int i = 0; i < 4; i++) {
        float inv = 1.f / l_run[i];
        #pragma unroll
        for (int j = 0; j < 4; j++)
            O[base + (size_t)(qt * 64 + r0 + i) * DMODEL + tx + 16 * j] = acc[i][j] * inv;
    }
}

// ---------------- residual add + LayerNorm (+ optional bf16 hi/lo out) ------
__device__ __forceinline__ float blockReduceSum(float val)
{
    __shared__ float red[8];
    __syncthreads();
    int lane = threadIdx.x & 31, wid = threadIdx.x >> 5;
    #pragma unroll
    for (int o = 16; o > 0; o >>= 1) val += __shfl_down_sync(0xffffffffu, val, o);
    if (lane == 0) red[wid] = val;
    __syncthreads();
    if (wid == 0) {
        val = (lane < 8) ? red[lane] : 0.f;
        #pragma unroll
        for (int o = 4; o > 0; o >>= 1) val += __shfl_down_sync(0xffffffffu, val, o);
        if (lane == 0) red[0] = val;
    }
    __syncthreads();
    return red[0];
}

__global__ __launch_bounds__(256)
void add_ln_kernel(const float* __restrict__ a, const float* __restrict__ res,
                   const float* __restrict__ g, const float* __restrict__ bt,
                   float* __restrict__ out,
                   __nv_bfloat16* __restrict__ ohi, __nv_bfloat16* __restrict__ olo)
{
    const int row = blockIdx.x;
    const int tid = threadIdx.x;
    float v[3];
    float sum = 0.f;
    #pragma unroll
    for (int i = 0; i < 3; i++) {
        int c = tid + i * 256;
        v[i] = a[(size_t)row * DMODEL + c] + res[(size_t)row * DMODEL + c];
        sum += v[i];
    }
    sum = blockReduceSum(sum);
    const float mu = sum * (1.f / DMODEL);
    float s2 = 0.f;
    #pragma unroll
    for (int i = 0; i < 3; i++) { float d = v[i] - mu; s2 += d * d; }
    s2 = blockReduceSum(s2);
    const float rs = rsqrtf(s2 * (1.f / DMODEL) + 1e-12f);
    #pragma unroll
    for (int i = 0; i < 3; i++) {
        int c = tid + i * 256;
        float val = (v[i] - mu) * rs * g[c] + bt[c];
        out[(size_t)row * DMODEL + c] = val;
        if (ohi) {
            float hf = __bfloat162float(__float2bfloat16_rn(val));
            ohi[(size_t)row * DMODEL + c] = __float2bfloat16_rn(val);
            olo[(size_t)row * DMODEL + c] = __float2bfloat16_rn(val - hf);
        }
    }
}

// ---------------- driver -----------------------------------------------------
extern "C" void kernel_launch(void* const* d_in, const int* in_sizes, int n_in,
                              void* d_out, int out_size)
{
    const float* x     = (const float*)d_in[0];
    const int*   amask = (const int*)  d_in[1];
    const float* Wq    = (const float*)d_in[2];
    const float* bq    = (const float*)d_in[3];
    const float* Wk    = (const float*)d_in[4];
    const float* bk    = (const float*)d_in[5];
    const float* Wv    = (const float*)d_in[6];
    const float* bv    = (const float*)d_in[7];
    const float* Wo    = (const float*)d_in[8];
    const float* bo    = (const float*)d_in[9];
    const float* ln1g  = (const float*)d_in[10];
    const float* ln1b  = (const float*)d_in[11];
    const float* W1    = (const float*)d_in[12];
    const float* b1    = (const float*)d_in[13];
    const float* W2    = (const float*)d_in[14];
    const float* b2    = (const float*)d_in[15];
    const float* ln2g  = (const float*)d_in[16];
    const float* ln2b  = (const float*)d_in[17];
    float* out = (float*)d_out;

    float *h, *h2, *q, *k, *v, *ctx, *tmp, *ff;
    __nv_bfloat16 *whi, *wlo, *ahi, *alo, *fhi, *flo;
    cudaGetSymbolAddress((void**)&h,   g_h);
    cudaGetSymbolAddress((void**)&h2,  g_h2);
    cudaGetSymbolAddress((void**)&q,   g_q);
    cudaGetSymbolAddress((void**)&k,   g_k);
    cudaGetSymbolAddress((void**)&v,   g_v);
    cudaGetSymbolAddress((void**)&ctx, g_ctx);
    cudaGetSymbolAddress((void**)&tmp, g_tmp);
    cudaGetSymbolAddress((void**)&ff,  g_ff);
    cudaGetSymbolAddress((void**)&whi, g_whi);
    cudaGetSymbolAddress((void**)&wlo, g_wlo);
    cudaGetSymbolAddress((void**)&ahi, g_ahi);
    cudaGetSymbolAddress((void**)&alo, g_alo);
    cudaGetSymbolAddress((void**)&fhi, g_fhi);
    cudaGetSymbolAddress((void**)&flo, g_flo);

    cudaFuncSetAttribute(hmma_gemm, cudaFuncAttributeMaxDynamicSharedMemorySize, GEMM_SMEM);
    cudaFuncSetAttribute(attn_kernel, cudaFuncAttributeMaxDynamicSharedMemorySize, ATT_SMEM);

    // ---- weight pre-conversion (once per launch) ----
    const int nDD4 = SZ_DD / 4;     // 884736
    const int nDF4 = SZ_DF / 4;     // 3538944
    f2bf<<<nDD4/256, 256>>>((const float4*)Wq, (uint2*)(whi+OQ),  (uint2*)(wlo+OQ),  nDD4);
    f2bf<<<nDD4/256, 256>>>((const float4*)Wk, (uint2*)(whi+OKk), (uint2*)(wlo+OKk), nDD4);
    f2bf<<<nDD4/256, 256>>>((const float4*)Wv, (uint2*)(whi+OV),  (uint2*)(wlo+OV),  nDD4);
    f2bf<<<nDD4/256, 256>>>((const float4*)Wo, (uint2*)(whi+OO),  (uint2*)(wlo+OO),  nDD4);
    f2bf<<<nDF4/256, 256>>>((const float4*)W1, (uint2*)(whi+O1),  (uint2*)(wlo+O1),  nDF4);
    f2bf<<<nDF4/256, 256>>>((const float4*)W2, (uint2*)(whi+O2),  (uint2*)(wlo+O2),  nDF4);

    const int nAct4 = NTOK * DMODEL / 4;   // 786432
    const dim3 gD(DMODEL / 128, NTOK / 128);   // (6, 32)
    const dim3 gF(FFD    / 128, NTOK / 128);   // (24, 32)
    const dim3 gA(SEQ / 64, NH, BATCH);        // (8, 12, 8)

    for (int i = 0; i < NL; i++) {
        const float* cur = (i == 0) ? x : h;
        const size_t wdd = (size_t)i * DMODEL * DMODEL;
        const size_t wdf = (size_t)i * DMODEL * FFD;

        if (i == 0)
            f2bf<<<nAct4/256, 256>>>((const float4*)x, (uint2*)ahi, (uint2*)alo, nAct4);

        hmma_gemm<<<gD, 256, GEMM_SMEM>>>(ahi, alo, whi+OQ+wdd, wlo+OQ+wdd,
                                          bq + i*DMODEL, q, 0, 0,
                                          NTOK, DMODEL, DMODEL, 0.125f, 0);
        hmma_gemm<<<gD, 256, GEMM_SMEM>>>(ahi, alo, whi+OKk+wdd, wlo+OKk+wdd,
                                          bk + i*DMODEL, k, 0, 0,
                                          NTOK, DMODEL, DMODEL, 1.f, 0);
        hmma_gemm<<<gD, 256, GEMM_SMEM>>>(ahi, alo, whi+OV+wdd, wlo+OV+wdd,
                                          bv + i*DMODEL, v, 0, 0,
                                          NTOK, DMODEL, DMODEL, 1.f, 0);
        attn_kernel<<<gA, 256, ATT_SMEM>>>(q, k, v, amask, ctx);
        f2bf<<<nAct4/256, 256>>>((const float4*)ctx, (uint2*)ahi, (uint2*)alo, nAct4);
        hmma_gemm<<<gD, 256, GEMM_SMEM>>>(ahi, alo, whi+OO+wdd, wlo+OO+wdd,
                                          bo + i*DMODEL, tmp, 0, 0,
                                          NTOK, DMODEL, DMODEL, 1.f, 0);
        add_ln_kernel<<<NTOK, 256>>>(tmp, cur, ln1g + i*DMODEL, ln1b + i*DMODEL,
                                     h2, ahi, alo);
        hmma_gemm<<<gF, 256, GEMM_SMEM>>>(ahi, alo, whi+O1+wdf, wlo+O1+wdf,
                                          b1 + i*FFD, ff, fhi, flo,
                                          NTOK, FFD, DMODEL, 1.f, 1);
        hmma_gemm<<<gD, 256, GEMM_SMEM>>>(fhi, flo, whi+O2+wdf, wlo+O2+wdf,
                                          b2 + i*DMODEL, tmp, 0, 0,
                                          NTOK, DMODEL, FFD, 1.f, 0);
        float* dst = (i == NL - 1) ? out : h;
        add_ln_kernel<<<NTOK, 256>>>(tmp, h2, ln2g + i*DMODEL, ln2b + i*DMODEL,
                                     dst, (i < NL-1) ? ahi : 0, (i < NL-1) ? alo : 0);
    }
}

// round 5
// speedup vs baseline: 2.4846x; 1.0491x over previous
#include <cuda_runtime.h>
#include <cuda_bf16.h>
#include <math.h>
#include <stdint.h>

#define DMODEL 768
#define FFD    3072
#define NL     6
#define NH     12
#define DH     64
#define SEQ    512
#define BATCH  8
#define NTOK   (BATCH*SEQ)   // 4096

#define SZ_DD  (NL*DMODEL*DMODEL)
#define SZ_DF  (NL*DMODEL*FFD)
#define OQ 0
#define OKk (SZ_DD)
#define OV  (2*SZ_DD)
#define OO  (3*SZ_DD)
#define O1  (4*SZ_DD)
#define O2  (4*SZ_DD + SZ_DF)
#define WTOT (4*SZ_DD + 2*SZ_DF)

// ---------------- scratch (static device globals; no runtime allocation) ----
__device__ float g_h  [NTOK*DMODEL];
__device__ float g_h2 [NTOK*DMODEL];
__device__ float g_q  [NTOK*DMODEL];
__device__ float g_k  [NTOK*DMODEL];
__device__ float g_v  [NTOK*DMODEL];
__device__ float g_tmp[NTOK*DMODEL];
__device__ float g_ff [NTOK*FFD];
__device__ __nv_bfloat16 g_whi[WTOT];
__device__ __nv_bfloat16 g_wlo[WTOT];
__device__ __nv_bfloat16 g_ahi[NTOK*DMODEL];
__device__ __nv_bfloat16 g_alo[NTOK*DMODEL];
__device__ __nv_bfloat16 g_chi[NTOK*DMODEL];
__device__ __nv_bfloat16 g_clo[NTOK*DMODEL];
__device__ __nv_bfloat16 g_fhi[NTOK*FFD];
__device__ __nv_bfloat16 g_flo[NTOK*FFD];

// ================= helpers ==================================================
__device__ __forceinline__ uint32_t smem_u32(const void* p) {
    uint32_t a;
    asm("{ .reg .u64 t; cvta.to.shared.u64 t, %1; cvt.u32.u64 %0, t; }"
        : "=r"(a) : "l"(p));
    return a;
}
__device__ __forceinline__ uint32_t packbf(float x, float y) {
    __nv_bfloat162 t = __floats2bfloat162_rn(x, y);
    return *(uint32_t*)&t;
}
__device__ __forceinline__ void cpa16(uint32_t dst, const void* src) {
    asm volatile("cp.async.cg.shared.global [%0], [%1], 16;"
                 :: "r"(dst), "l"(src) : "memory");
}
__device__ __forceinline__ void ldsm4(uint32_t* r, uint32_t addr) {
    asm volatile("ldmatrix.sync.aligned.m8n8.x4.shared.b16 {%0,%1,%2,%3}, [%4];"
                 : "=r"(r[0]), "=r"(r[1]), "=r"(r[2]), "=r"(r[3]) : "r"(addr));
}
__device__ __forceinline__ void ldsm4t(uint32_t* r, uint32_t addr) {
    asm volatile("ldmatrix.sync.aligned.m8n8.x4.trans.shared.b16 {%0,%1,%2,%3}, [%4];"
                 : "=r"(r[0]), "=r"(r[1]), "=r"(r[2]), "=r"(r[3]) : "r"(addr));
}
__device__ __forceinline__ void mma16816(float* d, const uint32_t* a,
                                         uint32_t b0, uint32_t b1) {
    asm volatile(
        "mma.sync.aligned.m16n8k16.row.col.f32.bf16.bf16.f32 "
        "{%0,%1,%2,%3}, {%4,%5,%6,%7}, {%8,%9}, {%0,%1,%2,%3};"
        : "+f"(d[0]), "+f"(d[1]), "+f"(d[2]), "+f"(d[3])
        : "r"(a[0]), "r"(a[1]), "r"(a[2]), "r"(a[3]), "r"(b0), "r"(b1));
}

// ================= fp32 -> bf16 hi/lo split conversion ======================
__global__ __launch_bounds__(256)
void f2bf(const float4* __restrict__ in, uint2* __restrict__ hi,
          uint2* __restrict__ lo, int n4)
{
    int i = blockIdx.x * 256 + threadIdx.x;
    if (i >= n4) return;
    float4 f = in[i];
    float hx = __bfloat162float(__float2bfloat16_rn(f.x));
    float hy = __bfloat162float(__float2bfloat16_rn(f.y));
    float hz = __bfloat162float(__float2bfloat16_rn(f.z));
    float hw = __bfloat162float(__float2bfloat16_rn(f.w));
    uint2 H = { packbf(hx, hy), packbf(hz, hw) };
    uint2 Lo = { packbf(f.x - hx, f.y - hy), packbf(f.z - hz, f.w - hw) };
    hi[i] = H;
    lo[i] = Lo;
}

// ================= split-bf16 HMMA GEMM (3-stage cp.async pipeline) =========
// stage layout (bytes): Ahi[0,10240) Alo[10240,20480) Bhi[20480,28672) Blo[28672,36864)
#define STG 36864
#define GEMM_SMEM (3*STG)

struct GemmJob {
    const __nv_bfloat16 *Bh, *Bl;
    const float* bias;
    float* C;
    __nv_bfloat16 *Chi, *Clo;
    float scale;
    int act;
};
struct GemmParams { GemmJob job[3]; };

__global__ __launch_bounds__(256, 1)
void hmma_gemm(const __nv_bfloat16* __restrict__ Ahi,
               const __nv_bfloat16* __restrict__ Alo,
               GemmParams P, int M, int N, int K)
{
    extern __shared__ char dsm[];
    const GemmJob& J = P.job[blockIdx.z];
    const __nv_bfloat16* __restrict__ Bhi = J.Bh;
    const __nv_bfloat16* __restrict__ Blo = J.Bl;
    const float* __restrict__ bias = J.bias;
    float* __restrict__ C = J.C;
    __nv_bfloat16 *Chi = J.Chi, *Clo = J.Clo;
    const float scale = J.scale;
    const int act = J.act;

    const uint32_t sb = smem_u32(dsm);
    const int tid = threadIdx.x;
    const int wid = tid >> 5, L = tid & 31;
    const int wm = wid & 3, wn = wid >> 2;
    const int row0 = blockIdx.y * 128, col0 = blockIdx.x * 128;

    float acc[2][8][4];
    #pragma unroll
    for (int i = 0; i < 2; i++)
        #pragma unroll
        for (int j = 0; j < 8; j++)
            #pragma unroll
            for (int t = 0; t < 4; t++) acc[i][j][t] = 0.f;

    const int aR0 = tid >> 2, aU = tid & 3;
    const int bR0 = tid >> 4, bU = tid & 15;
    const uint32_t aDst0 = (uint32_t)(aR0 * 80 + aU * 16);
    const uint32_t bDst0 = (uint32_t)(bR0 * 256 + ((bU ^ (bR0 & 7)) << 4));

    const __nv_bfloat16* aHb = Ahi + (size_t)(row0 + aR0) * K + aU * 8;
    const __nv_bfloat16* aLb = Alo + (size_t)(row0 + aR0) * K + aU * 8;
    const __nv_bfloat16* bHb = Bhi + (size_t)bR0 * N + col0 + bU * 8;
    const __nv_bfloat16* bLb = Blo + (size_t)bR0 * N + col0 + bU * 8;

    const int KB = K >> 5;

    #define ISSUE(kb) do {                                                  \
        const uint32_t stg_ = sb + (uint32_t)((kb) % 3) * STG;              \
        const int k0_ = (kb) * 32;                                          \
        cpa16(stg_ + aDst0,              aHb + k0_);                        \
        cpa16(stg_ + aDst0 + 10240,      aLb + k0_);                        \
        cpa16(stg_ + aDst0 + 5120,       aHb + k0_ + (size_t)64 * K);       \
        cpa16(stg_ + aDst0 + 5120+10240, aLb + k0_ + (size_t)64 * K);       \
        cpa16(stg_ + 20480 + bDst0,        bHb + (size_t)k0_ * N);          \
        cpa16(stg_ + 28672 + bDst0,        bLb + (size_t)k0_ * N);          \
        cpa16(stg_ + 20480 + bDst0 + 4096, bHb + (size_t)(k0_ + 16) * N);   \
        cpa16(stg_ + 28672 + bDst0 + 4096, bLb + (size_t)(k0_ + 16) * N);   \
        asm volatile("cp.async.commit_group;" ::: "memory");                \
    } while (0)

    ISSUE(0);
    ISSUE(1);

    const uint32_t aLane = (uint32_t)((wm * 32 + (L & 15)) * 80 + ((L >> 4) << 4));
    const uint32_t bRow  = (uint32_t)(L & 15);
    const uint32_t bSwzX = (uint32_t)(L & 7);
    const uint32_t bUL   = (uint32_t)(wn * 8 + (L >> 4));

    for (int kb = 0; kb < KB; kb++) {
        const uint32_t stg = sb + (uint32_t)(kb % 3) * STG;
        asm volatile("cp.async.wait_group 1;" ::: "memory");
        __syncthreads();
        if (kb + 2 < KB) ISSUE(kb + 2);

        #pragma unroll
        for (int ks = 0; ks < 2; ks++) {
            uint32_t ah[2][4], al[2][4];
            #pragma unroll
            for (int mt = 0; mt < 2; mt++) {
                uint32_t off = aLane + (uint32_t)(mt * 16 * 80 + ks * 32);
                ldsm4(ah[mt], stg + off);
                ldsm4(al[mt], stg + 10240 + off);
            }
            #pragma unroll
            for (int nj = 0; nj < 8; nj += 2) {
                uint32_t bh[4], bl[4];
                uint32_t off = (uint32_t)(ks * 16 + bRow) * 256
                             + (((bUL + nj) ^ bSwzX) << 4);
                ldsm4t(bh, stg + 20480 + off);
                ldsm4t(bl, stg + 28672 + off);
                #pragma unroll
                for (int mt = 0; mt < 2; mt++) {
                    mma16816(acc[mt][nj],   ah[mt], bh[0], bh[1]);
                    mma16816(acc[mt][nj+1], ah[mt], bh[2], bh[3]);
                    mma16816(acc[mt][nj],   ah[mt], bl[0], bl[1]);
                    mma16816(acc[mt][nj+1], ah[mt], bl[2], bl[3]);
                    mma16816(acc[mt][nj],   al[mt], bh[0], bh[1]);
                    mma16816(acc[mt][nj+1], al[mt], bh[2], bh[3]);
                }
            }
        }
    }
    #undef ISSUE

    asm volatile("cp.async.wait_group 0;" ::: "memory");
    __syncthreads();

    // ---- epilogue: stage through smem for coalesced stores -----------------
    float* sOut = (float*)dsm;
    const int gid = L >> 2, tig = L & 3;
    #pragma unroll
    for (int h = 0; h < 2; h++) {
        if (wn == h) {
            #pragma unroll
            for (int mt = 0; mt < 2; mt++) {
                #pragma unroll
                for (int nt = 0; nt < 8; nt++) {
                    const int srow = wm * 32 + mt * 16 + gid;
                    const int scol = nt * 8 + tig * 2;
                    const int gc   = col0 + h * 64 + scol;
                    float b0v = bias[gc], b1v = bias[gc + 1];
                    float v0 = (acc[mt][nt][0] + b0v) * scale;
                    float v1 = (acc[mt][nt][1] + b1v) * scale;
                    float v2 = (acc[mt][nt][2] + b0v) * scale;
                    float v3 = (acc[mt][nt][3] + b1v) * scale;
                    if (act) {
                        v0 = 0.5f*v0*(1.f+erff(v0*0.70710678118654752f));
                        v1 = 0.5f*v1*(1.f+erff(v1*0.70710678118654752f));
                        v2 = 0.5f*v2*(1.f+erff(v2*0.70710678118654752f));
                        v3 = 0.5f*v3*(1.f+erff(v3*0.70710678118654752f));
                    }
                    sOut[srow * 68 + scol]       = v0;
                    sOut[srow * 68 + scol + 1]   = v1;
                    sOut[(srow+8) * 68 + scol]   = v2;
                    sOut[(srow+8) * 68 + scol+1] = v3;
                }
            }
        }
        __syncthreads();
        #pragma unroll
        for (int i = 0; i < 8; i++) {
            const int f   = tid + i * 256;
            const int row = f >> 4;
            const int c4  = (f & 15) * 4;
            float4 v = *(const float4*)(sOut + row * 68 + c4);
            const size_t gidx = (size_t)(row0 + row) * N + col0 + h * 64 + c4;
            *(float4*)(C + gidx) = v;
            if (Chi) {
                float hx = __bfloat162float(__float2bfloat16_rn(v.x));
                float hy = __bfloat162float(__float2bfloat16_rn(v.y));
                float hz = __bfloat162float(__float2bfloat16_rn(v.z));
                float hw = __bfloat162float(__float2bfloat16_rn(v.w));
                uint2 H = { packbf(hx, hy), packbf(hz, hw) };
                uint2 Lo = { packbf(v.x - hx, v.y - hy), packbf(v.z - hz, v.w - hw) };
                *(uint2*)(Chi + gidx) = H;
                *(uint2*)(Clo + gidx) = Lo;
            }
        }
        __syncthreads();
    }
}

// ---------------- fused attention v2 (QT=64, bf16 hi/lo output) -------------
#define ATT_SMEM (12480*4)
__global__ __launch_bounds__(256)
void attn_kernel(const float* __restrict__ Q, const float* __restrict__ K,
                 const float* __restrict__ V, const int* __restrict__ mask,
                 __nv_bfloat16* __restrict__ Ohi, __nv_bfloat16* __restrict__ Olo)
{
    extern __shared__ float s[];
    float* qs  = s;
    float* kv  = s + 4096;
    float* sp  = s + 8256;
    float* msk = s + 12416;

    const int qt  = blockIdx.x;
    const int hh  = blockIdx.y;
    const int b   = blockIdx.z;
    const int tid = threadIdx.x;
    const int tx  = tid & 15;
    const int ty  = tid >> 4;
    const int r0  = ty * 4;

    const size_t base = (size_t)b * SEQ * DMODEL + (size_t)hh * DH;

    for (int l = tid; l < 1024; l += 256) {
        int r  = l >> 4;
        int c4 = (l & 15) * 4;
        float4 v = *(const float4*)(Q + base + (size_t)(qt * 64 + r) * DMODEL + c4);
        *(float4*)&qs[r * 64 + c4] = v;
    }

    float m_run[4], l_run[4], acc[4][4];
    #pragma unroll
    for (int i = 0; i < 4; i++) {
        m_run[i] = -1e30f; l_run[i] = 0.f;
        #pragma unroll
        for (int j = 0; j < 4; j++) acc[i][j] = 0.f;
    }

    for (int kt = 0; kt < SEQ / 64; kt++) {
        __syncthreads();
        for (int l = tid; l < 4096; l += 256) {
            int r = l >> 6, c = l & 63;
            kv[r * 65 + c] = K[base + (size_t)(kt * 64 + r) * DMODEL + c];
        }
        if (tid < 64) msk[tid] = (float)mask[b * SEQ + kt * 64 + tid];
        __syncthreads();

        float sc[4][4];
        #pragma unroll
        for (int i = 0; i < 4; i++)
            #pragma unroll
            for (int j = 0; j < 4; j++) sc[i][j] = 0.f;
        #pragma unroll 4
        for (int d = 0; d < DH; d++) {
            float qv[4];
            #pragma unroll
            for (int i = 0; i < 4; i++) qv[i] = qs[(r0 + i) * 64 + d];
            #pragma unroll
            for (int j = 0; j < 4; j++) {
                float kval = kv[(tx + 16 * j) * 65 + d];
                #pragma unroll
                for (int i = 0; i < 4; i++) sc[i][j] += qv[i] * kval;
            }
        }
        #pragma unroll
        for (int j = 0; j < 4; j++) {
            if (msk[tx + 16 * j] == 0.f) {
                #pragma unroll
                for (int i = 0; i < 4; i++) sc[i][j] = -1e9f;
            }
        }

        #pragma unroll
        for (int i = 0; i < 4; i++) {
            float mt = fmaxf(fmaxf(sc[i][0], sc[i][1]), fmaxf(sc[i][2], sc[i][3]));
            #pragma unroll
            for (int o = 8; o > 0; o >>= 1)
                mt = fmaxf(mt, __shfl_xor_sync(0xffffffffu, mt, o, 16));
            float mn = fmaxf(m_run[i], mt);
            float al = __expf(m_run[i] - mn);
            m_run[i] = mn;
            float ps = 0.f;
            #pragma unroll
            for (int j = 0; j < 4; j++) {
                float p = __expf(sc[i][j] - mn);
                ps += p;
                sp[(r0 + i) * 65 + tx + 16 * j] = p;
            }
            #pragma unroll
            for (int o = 8; o > 0; o >>= 1)
                ps += __shfl_xor_sync(0xffffffffu, ps, o, 16);
            l_run[i] = l_run[i] * al + ps;
            #pragma unroll
            for (int j = 0; j < 4; j++) acc[i][j] *= al;
        }
        __syncwarp();
        __syncthreads();
        for (int l = tid; l < 4096; l += 256) {
            int r = l >> 6, c = l & 63;
            kv[r * 65 + c] = V[base + (size_t)(kt * 64 + r) * DMODEL + c];
        }
        __syncthreads();

        #pragma unroll 4
        for (int k = 0; k < 64; k++) {
            float pv[4];
            #pragma unroll
            for (int i = 0; i < 4; i++) pv[i] = sp[(r0 + i) * 65 + k];
            #pragma unroll
            for (int j = 0; j < 4; j++) {
                float vval = kv[k * 65 + tx + 16 * j];
                #pragma unroll
                for (int i = 0; i < 4; i++) acc[i][j] += pv[i] * vval;
            }
        }
    }

    #pragma unroll
    for (int i = 0; i < 4; i++) {
        float inv = 1.f / l_run[i];
        #pragma unroll
        for (int j = 0; j < 4; j++) {
            float val = acc[i][j] * inv;
            size_t idx = base + (size_t)(qt * 64 + r0 + i) * DMODEL + tx + 16 * j;
            float hf = __bfloat162float(__float2bfloat16_rn(val));
            Ohi[idx] = __float2bfloat16_rn(val);
            Olo[idx] = __float2bfloat16_rn(val - hf);
        }
    }
}

// ---------------- residual add + LayerNorm (+ optional bf16 hi/lo out) ------
__device__ __forceinline__ float blockReduceSum(float val)
{
    __shared__ float red[8];
    __syncthreads();
    int lane = threadIdx.x & 31, wid = threadIdx.x >> 5;
    #pragma unroll
    for (int o = 16; o > 0; o >>= 1) val += __shfl_down_sync(0xffffffffu, val, o);
    if (lane == 0) red[wid] = val;
    __syncthreads();
    if (wid == 0) {
        val = (lane < 8) ? red[lane] : 0.f;
        #pragma unroll
        for (int o = 4; o > 0; o >>= 1) val += __shfl_down_sync(0xffffffffu, val, o);
        if (lane == 0) red[0] = val;
    }
    __syncthreads();
    return red[0];
}

__global__ __launch_bounds__(256)
void add_ln_kernel(const float* __restrict__ a, const float* __restrict__ res,
                   const float* __restrict__ g, const float* __restrict__ bt,
                   float* __restrict__ out,
                   __nv_bfloat16* __restrict__ ohi, __nv_bfloat16* __restrict__ olo)
{
    const int row = blockIdx.x;
    const int tid = threadIdx.x;
    float v[3];
    float sum = 0.f;
    #pragma unroll
    for (int i = 0; i < 3; i++) {
        int c = tid + i * 256;
        v[i] = a[(size_t)row * DMODEL + c] + res[(size_t)row * DMODEL + c];
        sum += v[i];
    }
    sum = blockReduceSum(sum);
    const float mu = sum * (1.f / DMODEL);
    float s2 = 0.f;
    #pragma unroll
    for (int i = 0; i < 3; i++) { float d = v[i] - mu; s2 += d * d; }
    s2 = blockReduceSum(s2);
    const float rs = rsqrtf(s2 * (1.f / DMODEL) + 1e-12f);
    #pragma unroll
    for (int i = 0; i < 3; i++) {
        int c = tid + i * 256;
        float val = (v[i] - mu) * rs * g[c] + bt[c];
        out[(size_t)row * DMODEL + c] = val;
        if (ohi) {
            float hf = __bfloat162float(__float2bfloat16_rn(val));
            ohi[(size_t)row * DMODEL + c] = __float2bfloat16_rn(val);
            olo[(size_t)row * DMODEL + c] = __float2bfloat16_rn(val - hf);
        }
    }
}

// ---------------- driver -----------------------------------------------------
extern "C" void kernel_launch(void* const* d_in, const int* in_sizes, int n_in,
                              void* d_out, int out_size)
{
    const float* x     = (const float*)d_in[0];
    const int*   amask = (const int*)  d_in[1];
    const float* Wq    = (const float*)d_in[2];
    const float* bq    = (const float*)d_in[3];
    const float* Wk    = (const float*)d_in[4];
    const float* bk    = (const float*)d_in[5];
    const float* Wv    = (const float*)d_in[6];
    const float* bv    = (const float*)d_in[7];
    const float* Wo    = (const float*)d_in[8];
    const float* bo    = (const float*)d_in[9];
    const float* ln1g  = (const float*)d_in[10];
    const float* ln1b  = (const float*)d_in[11];
    const float* W1    = (const float*)d_in[12];
    const float* b1    = (const float*)d_in[13];
    const float* W2    = (const float*)d_in[14];
    const float* b2    = (const float*)d_in[15];
    const float* ln2g  = (const float*)d_in[16];
    const float* ln2b  = (const float*)d_in[17];
    float* out = (float*)d_out;

    float *h, *h2, *q, *k, *v, *tmp;
    __nv_bfloat16 *whi, *wlo, *ahi, *alo, *chi, *clo, *fhi, *flo;
    float *ff;
    cudaGetSymbolAddress((void**)&h,   g_h);
    cudaGetSymbolAddress((void**)&h2,  g_h2);
    cudaGetSymbolAddress((void**)&q,   g_q);
    cudaGetSymbolAddress((void**)&k,   g_k);
    cudaGetSymbolAddress((void**)&v,   g_v);
    cudaGetSymbolAddress((void**)&tmp, g_tmp);
    cudaGetSymbolAddress((void**)&ff,  g_ff);
    cudaGetSymbolAddress((void**)&whi, g_whi);
    cudaGetSymbolAddress((void**)&wlo, g_wlo);
    cudaGetSymbolAddress((void**)&ahi, g_ahi);
    cudaGetSymbolAddress((void**)&alo, g_alo);
    cudaGetSymbolAddress((void**)&chi, g_chi);
    cudaGetSymbolAddress((void**)&clo, g_clo);
    cudaGetSymbolAddress((void**)&fhi, g_fhi);
    cudaGetSymbolAddress((void**)&flo, g_flo);

    cudaFuncSetAttribute(hmma_gemm, cudaFuncAttributeMaxDynamicSharedMemorySize, GEMM_SMEM);
    cudaFuncSetAttribute(attn_kernel, cudaFuncAttributeMaxDynamicSharedMemorySize, ATT_SMEM);

    const int nDD4 = SZ_DD / 4;
    const int nDF4 = SZ_DF / 4;
    f2bf<<<nDD4/256, 256>>>((const float4*)Wq, (uint2*)(whi+OQ),  (uint2*)(wlo+OQ),  nDD4);
    f2bf<<<nDD4/256, 256>>>((const float4*)Wk, (uint2*)(whi+OKk), (uint2*)(wlo+OKk), nDD4);
    f2bf<<<nDD4/256, 256>>>((const float4*)Wv, (uint2*)(whi+OV),  (uint2*)(wlo+OV),  nDD4);
    f2bf<<<nDD4/256, 256>>>((const float4*)Wo, (uint2*)(whi+OO),  (uint2*)(wlo+OO),  nDD4);
    f2bf<<<nDF4/256, 256>>>((const float4*)W1, (uint2*)(whi+O1),  (uint2*)(wlo+O1),  nDF4);
    f2bf<<<nDF4/256, 256>>>((const float4*)W2, (uint2*)(whi+O2),  (uint2*)(wlo+O2),  nDF4);

    const int nAct4 = NTOK * DMODEL / 4;
    const dim3 gQKV(DMODEL / 128, NTOK / 128, 3);  // 576 CTAs
    const dim3 gD(DMODEL / 128, NTOK / 128, 1);
    const dim3 gF(FFD    / 128, NTOK / 128, 1);
    const dim3 gA(SEQ / 64, NH, BATCH);

    f2bf<<<nAct4/256, 256>>>((const float4*)x, (uint2*)ahi, (uint2*)alo, nAct4);

    for (int i = 0; i < NL; i++) {
        const float* cur = (i == 0) ? x : h;
        const size_t wdd = (size_t)i * DMODEL * DMODEL;
        const size_t wdf = (size_t)i * DMODEL * FFD;

        GemmParams pq = {};
        pq.job[0] = { whi+OQ+wdd,  wlo+OQ+wdd,  bq + i*DMODEL, q, 0, 0, 0.125f, 0 };
        pq.job[1] = { whi+OKk+wdd, wlo+OKk+wdd, bk + i*DMODEL, k, 0, 0, 1.f,    0 };
        pq.job[2] = { whi+OV+wdd,  wlo+OV+wdd,  bv + i*DMODEL, v, 0, 0, 1.f,    0 };
        hmma_gemm<<<gQKV, 256, GEMM_SMEM>>>(ahi, alo, pq, NTOK, DMODEL, DMODEL);

        attn_kernel<<<gA, 256, ATT_SMEM>>>(q, k, v, amask, chi, clo);

        GemmParams po = {};
        po.job[0] = { whi+OO+wdd, wlo+OO+wdd, bo + i*DMODEL, tmp, 0, 0, 1.f, 0 };
        hmma_gemm<<<gD, 256, GEMM_SMEM>>>(chi, clo, po, NTOK, DMODEL, DMODEL);

        add_ln_kernel<<<NTOK, 256>>>(tmp, cur, ln1g + i*DMODEL, ln1b + i*DMODEL,
                                     h2, ahi, alo);

        GemmParams p1 = {};
        p1.job[0] = { whi+O1+wdf, wlo+O1+wdf, b1 + i*FFD, ff, fhi, flo, 1.f, 1 };
        hmma_gemm<<<gF, 256, GEMM_SMEM>>>(ahi, alo, p1, NTOK, FFD, DMODEL);

        GemmParams p2 = {};
        p2.job[0] = { whi+O2+wdf, wlo+O2+wdf, b2 + i*DMODEL, tmp, 0, 0, 1.f, 0 };
        hmma_gemm<<<gD, 256, GEMM_SMEM>>>(fhi, flo, p2, NTOK, DMODEL, FFD);

        float* dst = (i == NL - 1) ? out : h;
        add_ln_kernel<<<NTOK, 256>>>(tmp, h2, ln2g + i*DMODEL, ln2b + i*DMODEL,
                                     dst, (i < NL-1) ? ahi : 0, (i < NL-1) ? alo : 0);
    }
}

// round 6
// speedup vs baseline: 2.6652x; 1.0727x over previous
#include <cuda_runtime.h>
#include <cuda_bf16.h>
#include <math.h>
#include <stdint.h>

#define DMODEL 768
#define FFD    3072
#define NL     6
#define NH     12
#define DH     64
#define SEQ    512
#define BATCH  8
#define NTOK   (BATCH*SEQ)   // 4096

#define SZ_DD  (NL*DMODEL*DMODEL)
#define SZ_DF  (NL*DMODEL*FFD)
#define OQ 0
#define OKk (SZ_DD)
#define OV  (2*SZ_DD)
#define OO  (3*SZ_DD)
#define O1  (4*SZ_DD)
#define O2  (4*SZ_DD + SZ_DF)
#define WTOT (4*SZ_DD + 2*SZ_DF)

// ---------------- scratch (static device globals; no runtime allocation) ----
__device__ float g_h  [NTOK*DMODEL];
__device__ float g_h2 [NTOK*DMODEL];
__device__ float g_q  [NTOK*DMODEL];
__device__ float g_k  [NTOK*DMODEL];
__device__ float g_v  [NTOK*DMODEL];
__device__ float g_tmp[NTOK*DMODEL];
__device__ __nv_bfloat16 g_whi[WTOT];
__device__ __nv_bfloat16 g_wlo[WTOT];
__device__ __nv_bfloat16 g_ahi[NTOK*DMODEL];
__device__ __nv_bfloat16 g_alo[NTOK*DMODEL];
__device__ __nv_bfloat16 g_chi[NTOK*DMODEL];
__device__ __nv_bfloat16 g_clo[NTOK*DMODEL];
__device__ __nv_bfloat16 g_fhi[NTOK*FFD];
__device__ __nv_bfloat16 g_flo[NTOK*FFD];

// ================= helpers ==================================================
__device__ __forceinline__ uint32_t smem_u32(const void* p) {
    uint32_t a;
    asm("{ .reg .u64 t; cvta.to.shared.u64 t, %1; cvt.u32.u64 %0, t; }"
        : "=r"(a) : "l"(p));
    return a;
}
__device__ __forceinline__ uint32_t packbf(float x, float y) {
    __nv_bfloat162 t = __floats2bfloat162_rn(x, y);
    return *(uint32_t*)&t;
}
__device__ __forceinline__ void cpa16(uint32_t dst, const void* src) {
    asm volatile("cp.async.cg.shared.global [%0], [%1], 16;"
                 :: "r"(dst), "l"(src) : "memory");
}
__device__ __forceinline__ void ldsm4(uint32_t* r, uint32_t addr) {
    asm volatile("ldmatrix.sync.aligned.m8n8.x4.shared.b16 {%0,%1,%2,%3}, [%4];"
                 : "=r"(r[0]), "=r"(r[1]), "=r"(r[2]), "=r"(r[3]) : "r"(addr));
}
__device__ __forceinline__ void ldsm4t(uint32_t* r, uint32_t addr) {
    asm volatile("ldmatrix.sync.aligned.m8n8.x4.trans.shared.b16 {%0,%1,%2,%3}, [%4];"
                 : "=r"(r[0]), "=r"(r[1]), "=r"(r[2]), "=r"(r[3]) : "r"(addr));
}
__device__ __forceinline__ void mma16816(float* d, const uint32_t* a,
                                         uint32_t b0, uint32_t b1) {
    asm volatile(
        "mma.sync.aligned.m16n8k16.row.col.f32.bf16.bf16.f32 "
        "{%0,%1,%2,%3}, {%4,%5,%6,%7}, {%8,%9}, {%0,%1,%2,%3};"
        : "+f"(d[0]), "+f"(d[1]), "+f"(d[2]), "+f"(d[3])
        : "r"(a[0]), "r"(a[1]), "r"(a[2]), "r"(a[3]), "r"(b0), "r"(b1));
}

// ================= fp32 -> bf16 hi/lo split conversion ======================
__global__ __launch_bounds__(256)
void f2bf(const float4* __restrict__ in, uint2* __restrict__ hi,
          uint2* __restrict__ lo, int n4)
{
    int i = blockIdx.x * 256 + threadIdx.x;
    if (i >= n4) return;
    float4 f = in[i];
    float hx = __bfloat162float(__float2bfloat16_rn(f.x));
    float hy = __bfloat162float(__float2bfloat16_rn(f.y));
    float hz = __bfloat162float(__float2bfloat16_rn(f.z));
    float hw = __bfloat162float(__float2bfloat16_rn(f.w));
    uint2 H = { packbf(hx, hy), packbf(hz, hw) };
    uint2 Lo = { packbf(f.x - hx, f.y - hy), packbf(f.z - hz, f.w - hw) };
    hi[i] = H;
    lo[i] = Lo;
}

// ================= split-bf16 HMMA GEMM v3 ==================================
// 128 threads/CTA, 4 warps (64x64 warp tile), 128x128 CTA tile, BK=32,
// 2-stage cp.async, 2 CTAs/SM.
// stage layout: Ahi[0,10240) Alo[10240,20480) Bhi[20480,28672) Blo[28672,36864)
#define STG 36864
#define GEMM_SMEM (2*STG)

struct GemmJob {
    const __nv_bfloat16 *Bh, *Bl;
    const float* bias;
    float* C;
    __nv_bfloat16 *Chi, *Clo;
    float scale;
    int act;
};
struct GemmParams { GemmJob job[3]; };

__global__ __launch_bounds__(128, 2)
void hmma_gemm(const __nv_bfloat16* __restrict__ Ahi,
               const __nv_bfloat16* __restrict__ Alo,
               GemmParams P, int M, int N, int K)
{
    extern __shared__ char dsm[];
    const GemmJob& J = P.job[blockIdx.z];
    const __nv_bfloat16* __restrict__ Bhi = J.Bh;
    const __nv_bfloat16* __restrict__ Blo = J.Bl;

    const uint32_t sb = smem_u32(dsm);
    const int tid = threadIdx.x;
    const int wid = tid >> 5, L = tid & 31;
    const int wm = wid & 1, wn = wid >> 1;
    const int row0 = blockIdx.y * 128, col0 = blockIdx.x * 128;

    float acc[4][8][4];
    #pragma unroll
    for (int i = 0; i < 4; i++)
        #pragma unroll
        for (int j = 0; j < 8; j++)
            #pragma unroll
            for (int t = 0; t < 4; t++) acc[i][j][t] = 0.f;

    const int aR = tid >> 2, aU = tid & 3;      // rows 0..31 (4 passes), 4x16B units
    const int bR = tid >> 4, bU = tid & 15;     // rows 0..7 (4 passes), 16 units
    const uint32_t aDst = (uint32_t)(aR * 80 + aU * 16);
    const uint32_t bDst = (uint32_t)(bR * 256 + ((bU ^ (bR & 7)) << 4));

    const __nv_bfloat16* aHb = Ahi + (size_t)(row0 + aR) * K + aU * 8;
    const __nv_bfloat16* aLb = Alo + (size_t)(row0 + aR) * K + aU * 8;
    const __nv_bfloat16* bHb = Bhi + (size_t)bR * N + col0 + bU * 8;
    const __nv_bfloat16* bLb = Blo + (size_t)bR * N + col0 + bU * 8;

    const int KB = K >> 5;

    #define ISSUE(kb) do {                                                    \
        const uint32_t stg_ = sb + (uint32_t)((kb) & 1) * STG;                \
        const int k0_ = (kb) * 32;                                            \
        _Pragma("unroll")                                                     \
        for (int p = 0; p < 4; p++) {                                         \
            cpa16(stg_ + aDst + p * 2560,         aHb + k0_ + (size_t)(p*32) * K); \
            cpa16(stg_ + 10240 + aDst + p * 2560, aLb + k0_ + (size_t)(p*32) * K); \
            cpa16(stg_ + 20480 + bDst + p * 2048, bHb + (size_t)(k0_ + p*8) * N);  \
            cpa16(stg_ + 28672 + bDst + p * 2048, bLb + (size_t)(k0_ + p*8) * N);  \
        }                                                                     \
        asm volatile("cp.async.commit_group;" ::: "memory");                  \
    } while (0)

    ISSUE(0);

    const uint32_t aLane = (uint32_t)((wm * 64 + (L & 15)) * 80 + ((L >> 4) << 4));
    const uint32_t bRow  = (uint32_t)(L & 15);
    const uint32_t bSwzX = (uint32_t)(L & 7);
    const uint32_t bUL   = (uint32_t)(wn * 8 + (L >> 4));

    for (int kb = 0; kb < KB; kb++) {
        const uint32_t stg = sb + (uint32_t)(kb & 1) * STG;
        asm volatile("cp.async.wait_group 0;" ::: "memory");
        __syncthreads();
        if (kb + 1 < KB) ISSUE(kb + 1);

        #pragma unroll
        for (int ks = 0; ks < 2; ks++) {
            uint32_t ah[4][4], al[4][4];
            #pragma unroll
            for (int mt = 0; mt < 4; mt++) {
                uint32_t off = aLane + (uint32_t)(mt * 16 * 80 + ks * 32);
                ldsm4(ah[mt], stg + off);
                ldsm4(al[mt], stg + 10240 + off);
            }
            #pragma unroll
            for (int nj = 0; nj < 8; nj += 2) {
                uint32_t bh[4], bl[4];
                uint32_t off = (uint32_t)(ks * 16 + bRow) * 256
                             + (((bUL + nj) ^ bSwzX) << 4);
                ldsm4t(bh, stg + 20480 + off);
                ldsm4t(bl, stg + 28672 + off);
                #pragma unroll
                for (int mt = 0; mt < 4; mt++) {
                    mma16816(acc[mt][nj],   ah[mt], bh[0], bh[1]);
                    mma16816(acc[mt][nj+1], ah[mt], bh[2], bh[3]);
                    mma16816(acc[mt][nj],   ah[mt], bl[0], bl[1]);
                    mma16816(acc[mt][nj+1], ah[mt], bl[2], bl[3]);
                    mma16816(acc[mt][nj],   al[mt], bh[0], bh[1]);
                    mma16816(acc[mt][nj+1], al[mt], bh[2], bh[3]);
                }
            }
        }
        __syncthreads();
    }
    #undef ISSUE

    // ---- epilogue ----------------------------------------------------------
    const float* bias = J.bias;
    float* C = J.C;
    __nv_bfloat16 *Chi = J.Chi, *Clo = J.Clo;
    const float scale = J.scale;
    const int act = J.act;

    float* sOut = (float*)dsm;               // 128 x 68 fp32
    const int gid = L >> 2, tig = L & 3;
    #pragma unroll
    for (int h = 0; h < 2; h++) {
        if (wn == h) {
            #pragma unroll
            for (int mt = 0; mt < 4; mt++) {
                #pragma unroll
                for (int nt = 0; nt < 8; nt++) {
                    const int srow = wm * 64 + mt * 16 + gid;
                    const int scol = nt * 8 + tig * 2;
                    const int gc   = col0 + h * 64 + scol;
                    float b0v = bias[gc], b1v = bias[gc + 1];
                    float v0 = (acc[mt][nt][0] + b0v) * scale;
                    float v1 = (acc[mt][nt][1] + b1v) * scale;
                    float v2 = (acc[mt][nt][2] + b0v) * scale;
                    float v3 = (acc[mt][nt][3] + b1v) * scale;
                    if (act) {
                        v0 = 0.5f*v0*(1.f+erff(v0*0.70710678118654752f));
                        v1 = 0.5f*v1*(1.f+erff(v1*0.70710678118654752f));
                        v2 = 0.5f*v2*(1.f+erff(v2*0.70710678118654752f));
                        v3 = 0.5f*v3*(1.f+erff(v3*0.70710678118654752f));
                    }
                    sOut[srow * 68 + scol]       = v0;
                    sOut[srow * 68 + scol + 1]   = v1;
                    sOut[(srow+8) * 68 + scol]   = v2;
                    sOut[(srow+8) * 68 + scol+1] = v3;
                }
            }
        }
        __syncthreads();
        #pragma unroll
        for (int i = 0; i < 16; i++) {
            const int f   = tid + i * 128;
            const int row = f >> 4;
            const int c4  = (f & 15) * 4;
            float4 v = *(const float4*)(sOut + row * 68 + c4);
            const size_t gidx = (size_t)(row0 + row) * N + col0 + h * 64 + c4;
            if (C) *(float4*)(C + gidx) = v;
            if (Chi) {
                float hx = __bfloat162float(__float2bfloat16_rn(v.x));
                float hy = __bfloat162float(__float2bfloat16_rn(v.y));
                float hz = __bfloat162float(__float2bfloat16_rn(v.z));
                float hw = __bfloat162float(__float2bfloat16_rn(v.w));
                uint2 H = { packbf(hx, hy), packbf(hz, hw) };
                uint2 Lo = { packbf(v.x - hx, v.y - hy), packbf(v.z - hz, v.w - hw) };
                *(uint2*)(Chi + gidx) = H;
                *(uint2*)(Clo + gidx) = Lo;
            }
        }
        __syncthreads();
    }
}

// ---------------- fused attention v2 (QT=64, bf16 hi/lo output) -------------
#define ATT_SMEM (12480*4)
__global__ __launch_bounds__(256)
void attn_kernel(const float* __restrict__ Q, const float* __restrict__ K,
                 const float* __restrict__ V, const int* __restrict__ mask,
                 __nv_bfloat16* __restrict__ Ohi, __nv_bfloat16* __restrict__ Olo)
{
    extern __shared__ float s[];
    float* qs  = s;
    float* kv  = s + 4096;
    float* sp  = s + 8256;
    float* msk = s + 12416;

    const int qt  = blockIdx.x;
    const int hh  = blockIdx.y;
    const int b   = blockIdx.z;
    const int tid = threadIdx.x;
    const int tx  = tid & 15;
    const int ty  = tid >> 4;
    const int r0  = ty * 4;

    const size_t base = (size_t)b * SEQ * DMODEL + (size_t)hh * DH;

    for (int l = tid; l < 1024; l += 256) {
        int r  = l >> 4;
        int c4 = (l & 15) * 4;
        float4 v = *(const float4*)(Q + base + (size_t)(qt * 64 + r) * DMODEL + c4);
        *(float4*)&qs[r * 64 + c4] = v;
    }

    float m_run[4], l_run[4], acc[4][4];
    #pragma unroll
    for (int i = 0; i < 4; i++) {
        m_run[i] = -1e30f; l_run[i] = 0.f;
        #pragma unroll
        for (int j = 0; j < 4; j++) acc[i][j] = 0.f;
    }

    for (int kt = 0; kt < SEQ / 64; kt++) {
        __syncthreads();
        for (int l = tid; l < 4096; l += 256) {
            int r = l >> 6, c = l & 63;
            kv[r * 65 + c] = K[base + (size_t)(kt * 64 + r) * DMODEL + c];
        }
        if (tid < 64) msk[tid] = (float)mask[b * SEQ + kt * 64 + tid];
        __syncthreads();

        float sc[4][4];
        #pragma unroll
        for (int i = 0; i < 4; i++)
            #pragma unroll
            for (int j = 0; j < 4; j++) sc[i][j] = 0.f;
        #pragma unroll 4
        for (int d = 0; d < DH; d++) {
            float qv[4];
            #pragma unroll
            for (int i = 0; i < 4; i++) qv[i] = qs[(r0 + i) * 64 + d];
            #pragma unroll
            for (int j = 0; j < 4; j++) {
                float kval = kv[(tx + 16 * j) * 65 + d];
                #pragma unroll
                for (int i = 0; i < 4; i++) sc[i][j] += qv[i] * kval;
            }
        }
        #pragma unroll
        for (int j = 0; j < 4; j++) {
            if (msk[tx + 16 * j] == 0.f) {
                #pragma unroll
                for (int i = 0; i < 4; i++) sc[i][j] = -1e9f;
            }
        }

        #pragma unroll
        for (int i = 0; i < 4; i++) {
            float mt = fmaxf(fmaxf(sc[i][0], sc[i][1]), fmaxf(sc[i][2], sc[i][3]));
            #pragma unroll
            for (int o = 8; o > 0; o >>= 1)
                mt = fmaxf(mt, __shfl_xor_sync(0xffffffffu, mt, o, 16));
            float mn = fmaxf(m_run[i], mt);
            float al = __expf(m_run[i] - mn);
            m_run[i] = mn;
            float ps = 0.f;
            #pragma unroll
            for (int j = 0; j < 4; j++) {
                float p = __expf(sc[i][j] - mn);
                ps += p;
                sp[(r0 + i) * 65 + tx + 16 * j] = p;
            }
            #pragma unroll
            for (int o = 8; o > 0; o >>= 1)
                ps += __shfl_xor_sync(0xffffffffu, ps, o, 16);
            l_run[i] = l_run[i] * al + ps;
            #pragma unroll
            for (int j = 0; j < 4; j++) acc[i][j] *= al;
        }
        __syncwarp();
        __syncthreads();
        for (int l = tid; l < 4096; l += 256) {
            int r = l >> 6, c = l & 63;
            kv[r * 65 + c] = V[base + (size_t)(kt * 64 + r) * DMODEL + c];
        }
        __syncthreads();

        #pragma unroll 4
        for (int k = 0; k < 64; k++) {
            float pv[4];
            #pragma unroll
            for (int i = 0; i < 4; i++) pv[i] = sp[(r0 + i) * 65 + k];
            #pragma unroll
            for (int j = 0; j < 4; j++) {
                float vval = kv[k * 65 + tx + 16 * j];
                #pragma unroll
                for (int i = 0; i < 4; i++) acc[i][j] += pv[i] * vval;
            }
        }
    }

    #pragma unroll
    for (int i = 0; i < 4; i++) {
        float inv = 1.f / l_run[i];
        #pragma unroll
        for (int j = 0; j < 4; j++) {
            float val = acc[i][j] * inv;
            size_t idx = base + (size_t)(qt * 64 + r0 + i) * DMODEL + tx + 16 * j;
            float hf = __bfloat162float(__float2bfloat16_rn(val));
            Ohi[idx] = __float2bfloat16_rn(val);
            Olo[idx] = __float2bfloat16_rn(val - hf);
        }
    }
}

// ---------------- residual add + LayerNorm (+ optional bf16 hi/lo out) ------
__device__ __forceinline__ float blockReduceSum(float val)
{
    __shared__ float red[8];
    __syncthreads();
    int lane = threadIdx.x & 31, wid = threadIdx.x >> 5;
    #pragma unroll
    for (int o = 16; o > 0; o >>= 1) val += __shfl_down_sync(0xffffffffu, val, o);
    if (lane == 0) red[wid] = val;
    __syncthreads();
    if (wid == 0) {
        val = (lane < 8) ? red[lane] : 0.f;
        #pragma unroll
        for (int o = 4; o > 0; o >>= 1) val += __shfl_down_sync(0xffffffffu, val, o);
        if (lane == 0) red[0] = val;
    }
    __syncthreads();
    return red[0];
}

__global__ __launch_bounds__(256)
void add_ln_kernel(const float* __restrict__ a, const float* __restrict__ res,
                   const float* __restrict__ g, const float* __restrict__ bt,
                   float* __restrict__ out,
                   __nv_bfloat16* __restrict__ ohi, __nv_bfloat16* __restrict__ olo)
{
    const int row = blockIdx.x;
    const int tid = threadIdx.x;
    float v[3];
    float sum = 0.f;
    #pragma unroll
    for (int i = 0; i < 3; i++) {
        int c = tid + i * 256;
        v[i] = a[(size_t)row * DMODEL + c] + res[(size_t)row * DMODEL + c];
        sum += v[i];
    }
    sum = blockReduceSum(sum);
    const float mu = sum * (1.f / DMODEL);
    float s2 = 0.f;
    #pragma unroll
    for (int i = 0; i < 3; i++) { float d = v[i] - mu; s2 += d * d; }
    s2 = blockReduceSum(s2);
    const float rs = rsqrtf(s2 * (1.f / DMODEL) + 1e-12f);
    #pragma unroll
    for (int i = 0; i < 3; i++) {
        int c = tid + i * 256;
        float val = (v[i] - mu) * rs * g[c] + bt[c];
        out[(size_t)row * DMODEL + c] = val;
        if (ohi) {
            float hf = __bfloat162float(__float2bfloat16_rn(val));
            ohi[(size_t)row * DMODEL + c] = __float2bfloat16_rn(val);
            olo[(size_t)row * DMODEL + c] = __float2bfloat16_rn(val - hf);
        }
    }
}

// ---------------- driver -----------------------------------------------------
extern "C" void kernel_launch(void* const* d_in, const int* in_sizes, int n_in,
                              void* d_out, int out_size)
{
    const float* x     = (const float*)d_in[0];
    const int*   amask = (const int*)  d_in[1];
    const float* Wq    = (const float*)d_in[2];
    const float* bq    = (const float*)d_in[3];
    const float* Wk    = (const float*)d_in[4];
    const float* bk    = (const float*)d_in[5];
    const float* Wv    = (const float*)d_in[6];
    const float* bv    = (const float*)d_in[7];
    const float* Wo    = (const float*)d_in[8];
    const float* bo    = (const float*)d_in[9];
    const float* ln1g  = (const float*)d_in[10];
    const float* ln1b  = (const float*)d_in[11];
    const float* W1    = (const float*)d_in[12];
    const float* b1    = (const float*)d_in[13];
    const float* W2    = (const float*)d_in[14];
    const float* b2    = (const float*)d_in[15];
    const float* ln2g  = (const float*)d_in[16];
    const float* ln2b  = (const float*)d_in[17];
    float* out = (float*)d_out;

    float *h, *h2, *q, *k, *v, *tmp;
    __nv_bfloat16 *whi, *wlo, *ahi, *alo, *chi, *clo, *fhi, *flo;
    cudaGetSymbolAddress((void**)&h,   g_h);
    cudaGetSymbolAddress((void**)&h2,  g_h2);
    cudaGetSymbolAddress((void**)&q,   g_q);
    cudaGetSymbolAddress((void**)&k,   g_k);
    cudaGetSymbolAddress((void**)&v,   g_v);
    cudaGetSymbolAddress((void**)&tmp, g_tmp);
    cudaGetSymbolAddress((void**)&whi, g_whi);
    cudaGetSymbolAddress((void**)&wlo, g_wlo);
    cudaGetSymbolAddress((void**)&ahi, g_ahi);
    cudaGetSymbolAddress((void**)&alo, g_alo);
    cudaGetSymbolAddress((void**)&chi, g_chi);
    cudaGetSymbolAddress((void**)&clo, g_clo);
    cudaGetSymbolAddress((void**)&fhi, g_fhi);
    cudaGetSymbolAddress((void**)&flo, g_flo);

    cudaFuncSetAttribute(hmma_gemm, cudaFuncAttributeMaxDynamicSharedMemorySize, GEMM_SMEM);
    cudaFuncSetAttribute(attn_kernel, cudaFuncAttributeMaxDynamicSharedMemorySize, ATT_SMEM);

    const int nDD4 = SZ_DD / 4;
    const int nDF4 = SZ_DF / 4;
    f2bf<<<nDD4/256, 256>>>((const float4*)Wq, (uint2*)(whi+OQ),  (uint2*)(wlo+OQ),  nDD4);
    f2bf<<<nDD4/256, 256>>>((const float4*)Wk, (uint2*)(whi+OKk), (uint2*)(wlo+OKk), nDD4);
    f2bf<<<nDD4/256, 256>>>((const float4*)Wv, (uint2*)(whi+OV),  (uint2*)(wlo+OV),  nDD4);
    f2bf<<<nDD4/256, 256>>>((const float4*)Wo, (uint2*)(whi+OO),  (uint2*)(wlo+OO),  nDD4);
    f2bf<<<nDF4/256, 256>>>((const float4*)W1, (uint2*)(whi+O1),  (uint2*)(wlo+O1),  nDF4);
    f2bf<<<nDF4/256, 256>>>((const float4*)W2, (uint2*)(whi+O2),  (uint2*)(wlo+O2),  nDF4);

    const int nAct4 = NTOK * DMODEL / 4;
    const dim3 gQKV(DMODEL / 128, NTOK / 128, 3);
    const dim3 gD(DMODEL / 128, NTOK / 128, 1);
    const dim3 gF(FFD    / 128, NTOK / 128, 1);
    const dim3 gA(SEQ / 64, NH, BATCH);

    f2bf<<<nAct4/256, 256>>>((const float4*)x, (uint2*)ahi, (uint2*)alo, nAct4);

    for (int i = 0; i < NL; i++) {
        const float* cur = (i == 0) ? x : h;
        const size_t wdd = (size_t)i * DMODEL * DMODEL;
        const size_t wdf = (size_t)i * DMODEL * FFD;

        GemmParams pq = {};
        pq.job[0] = { whi+OQ+wdd,  wlo+OQ+wdd,  bq + i*DMODEL, q, 0, 0, 0.125f, 0 };
        pq.job[1] = { whi+OKk+wdd, wlo+OKk+wdd, bk + i*DMODEL, k, 0, 0, 1.f,    0 };
        pq.job[2] = { whi+OV+wdd,  wlo+OV+wdd,  bv + i*DMODEL, v, 0, 0, 1.f,    0 };
        hmma_gemm<<<gQKV, 128, GEMM_SMEM>>>(ahi, alo, pq, NTOK, DMODEL, DMODEL);

        attn_kernel<<<gA, 256, ATT_SMEM>>>(q, k, v, amask, chi, clo);

        GemmParams po = {};
        po.job[0] = { whi+OO+wdd, wlo+OO+wdd, bo + i*DMODEL, tmp, 0, 0, 1.f, 0 };
        hmma_gemm<<<gD, 128, GEMM_SMEM>>>(chi, clo, po, NTOK, DMODEL, DMODEL);

        add_ln_kernel<<<NTOK, 256>>>(tmp, cur, ln1g + i*DMODEL, ln1b + i*DMODEL,
                                     h2, ahi, alo);

        GemmParams p1 = {};
        p1.job[0] = { whi+O1+wdf, wlo+O1+wdf, b1 + i*FFD, 0, fhi, flo, 1.f, 1 };
        hmma_gemm<<<gF, 128, GEMM_SMEM>>>(ahi, alo, p1, NTOK, FFD, DMODEL);

        GemmParams p2 = {};
        p2.job[0] = { whi+O2+wdf, wlo+O2+wdf, b2 + i*DMODEL, tmp, 0, 0, 1.f, 0 };
        hmma_gemm<<<gD, 128, GEMM_SMEM>>>(fhi, flo, p2, NTOK, DMODEL, FFD);

        float* dst = (i == NL - 1) ? out : h;
        add_ln_kernel<<<NTOK, 256>>>(tmp, h2, ln2g + i*DMODEL, ln2b + i*DMODEL,
                                     dst, (i < NL-1) ? ahi : 0, (i < NL-1) ? alo : 0);
    }
}

// round 7
// speedup vs baseline: 3.2999x; 1.2381x over previous
#include <cuda_runtime.h>
#include <cuda_bf16.h>
#include <math.h>
#include <stdint.h>

#define DMODEL 768
#define FFD    3072
#define NL     6
#define NH     12
#define DH     64
#define SEQ    512
#define BATCH  8
#define NTOK   (BATCH*SEQ)   // 4096

#define SZ_DD  (NL*DMODEL*DMODEL)
#define SZ_DF  (NL*DMODEL*FFD)
#define OQ 0
#define OKk (SZ_DD)
#define OV  (2*SZ_DD)
#define OO  (3*SZ_DD)
#define O1  (4*SZ_DD)
#define O2  (4*SZ_DD + SZ_DF)
#define WTOT (4*SZ_DD + 2*SZ_DF)

// ---------------- scratch (static device globals; no runtime allocation) ----
__device__ float g_h  [NTOK*DMODEL];
__device__ float g_h2 [NTOK*DMODEL];
__device__ float g_tmp[NTOK*DMODEL];
__device__ __nv_bfloat16 g_whi[WTOT];
__device__ __nv_bfloat16 g_wlo[WTOT];
__device__ __nv_bfloat16 g_ahi[NTOK*DMODEL];
__device__ __nv_bfloat16 g_alo[NTOK*DMODEL];
__device__ __nv_bfloat16 g_qhi[NTOK*DMODEL];
__device__ __nv_bfloat16 g_qlo[NTOK*DMODEL];
__device__ __nv_bfloat16 g_khi[NTOK*DMODEL];
__device__ __nv_bfloat16 g_klo[NTOK*DMODEL];
__device__ __nv_bfloat16 g_vhi[NTOK*DMODEL];
__device__ __nv_bfloat16 g_vlo[NTOK*DMODEL];
__device__ __nv_bfloat16 g_chi[NTOK*DMODEL];
__device__ __nv_bfloat16 g_clo[NTOK*DMODEL];
__device__ __nv_bfloat16 g_fhi[NTOK*FFD];
__device__ __nv_bfloat16 g_flo[NTOK*FFD];

// ================= helpers ==================================================
__device__ __forceinline__ uint32_t smem_u32(const void* p) {
    uint32_t a;
    asm("{ .reg .u64 t; cvta.to.shared.u64 t, %1; cvt.u32.u64 %0, t; }"
        : "=r"(a) : "l"(p));
    return a;
}
__device__ __forceinline__ uint32_t packbf(float x, float y) {
    __nv_bfloat162 t = __floats2bfloat162_rn(x, y);
    return *(uint32_t*)&t;
}
__device__ __forceinline__ void cpa16(uint32_t dst, const void* src) {
    asm volatile("cp.async.cg.shared.global [%0], [%1], 16;"
                 :: "r"(dst), "l"(src) : "memory");
}
__device__ __forceinline__ void ldsm4(uint32_t* r, uint32_t addr) {
    asm volatile("ldmatrix.sync.aligned.m8n8.x4.shared.b16 {%0,%1,%2,%3}, [%4];"
                 : "=r"(r[0]), "=r"(r[1]), "=r"(r[2]), "=r"(r[3]) : "r"(addr));
}
__device__ __forceinline__ void ldsm4t(uint32_t* r, uint32_t addr) {
    asm volatile("ldmatrix.sync.aligned.m8n8.x4.trans.shared.b16 {%0,%1,%2,%3}, [%4];"
                 : "=r"(r[0]), "=r"(r[1]), "=r"(r[2]), "=r"(r[3]) : "r"(addr));
}
__device__ __forceinline__ void mma16816(float* d, const uint32_t* a,
                                         uint32_t b0, uint32_t b1) {
    asm volatile(
        "mma.sync.aligned.m16n8k16.row.col.f32.bf16.bf16.f32 "
        "{%0,%1,%2,%3}, {%4,%5,%6,%7}, {%8,%9}, {%0,%1,%2,%3};"
        : "+f"(d[0]), "+f"(d[1]), "+f"(d[2]), "+f"(d[3])
        : "r"(a[0]), "r"(a[1]), "r"(a[2]), "r"(a[3]), "r"(b0), "r"(b1));
}

// ================= fp32 -> bf16 hi/lo split conversion ======================
__global__ __launch_bounds__(256)
void f2bf(const float4* __restrict__ in, uint2* __restrict__ hi,
          uint2* __restrict__ lo, int n4)
{
    int i = blockIdx.x * 256 + threadIdx.x;
    if (i >= n4) return;
    float4 f = in[i];
    float hx = __bfloat162float(__float2bfloat16_rn(f.x));
    float hy = __bfloat162float(__float2bfloat16_rn(f.y));
    float hz = __bfloat162float(__float2bfloat16_rn(f.z));
    float hw = __bfloat162float(__float2bfloat16_rn(f.w));
    uint2 H = { packbf(hx, hy), packbf(hz, hw) };
    uint2 Lo = { packbf(f.x - hx, f.y - hy), packbf(f.z - hz, f.w - hw) };
    hi[i] = H;
    lo[i] = Lo;
}

// ================= split-bf16 HMMA GEMM v3 ==================================
#define STG 36864
#define GEMM_SMEM (2*STG)

struct GemmJob {
    const __nv_bfloat16 *Bh, *Bl;
    const float* bias;
    float* C;
    __nv_bfloat16 *Chi, *Clo;
    float scale;
    int act;
};
struct GemmParams { GemmJob job[3]; };

__global__ __launch_bounds__(128, 2)
void hmma_gemm(const __nv_bfloat16* __restrict__ Ahi,
               const __nv_bfloat16* __restrict__ Alo,
               GemmParams P, int M, int N, int K)
{
    extern __shared__ char dsm[];
    const GemmJob& J = P.job[blockIdx.z];
    const __nv_bfloat16* __restrict__ Bhi = J.Bh;
    const __nv_bfloat16* __restrict__ Blo = J.Bl;

    const uint32_t sb = smem_u32(dsm);
    const int tid = threadIdx.x;
    const int wid = tid >> 5, L = tid & 31;
    const int wm = wid & 1, wn = wid >> 1;
    const int row0 = blockIdx.y * 128, col0 = blockIdx.x * 128;

    float acc[4][8][4];
    #pragma unroll
    for (int i = 0; i < 4; i++)
        #pragma unroll
        for (int j = 0; j < 8; j++)
            #pragma unroll
            for (int t = 0; t < 4; t++) acc[i][j][t] = 0.f;

    const int aR = tid >> 2, aU = tid & 3;
    const int bR = tid >> 4, bU = tid & 15;
    const uint32_t aDst = (uint32_t)(aR * 80 + aU * 16);
    const uint32_t bDst = (uint32_t)(bR * 256 + ((bU ^ (bR & 7)) << 4));

    const __nv_bfloat16* aHb = Ahi + (size_t)(row0 + aR) * K + aU * 8;
    const __nv_bfloat16* aLb = Alo + (size_t)(row0 + aR) * K + aU * 8;
    const __nv_bfloat16* bHb = Bhi + (size_t)bR * N + col0 + bU * 8;
    const __nv_bfloat16* bLb = Blo + (size_t)bR * N + col0 + bU * 8;

    const int KB = K >> 5;

    #define ISSUE(kb) do {                                                    \
        const uint32_t stg_ = sb + (uint32_t)((kb) & 1) * STG;                \
        const int k0_ = (kb) * 32;                                            \
        _Pragma("unroll")                                                     \
        for (int p = 0; p < 4; p++) {                                         \
            cpa16(stg_ + aDst + p * 2560,         aHb + k0_ + (size_t)(p*32) * K); \
            cpa16(stg_ + 10240 + aDst + p * 2560, aLb + k0_ + (size_t)(p*32) * K); \
            cpa16(stg_ + 20480 + bDst + p * 2048, bHb + (size_t)(k0_ + p*8) * N);  \
            cpa16(stg_ + 28672 + bDst + p * 2048, bLb + (size_t)(k0_ + p*8) * N);  \
        }                                                                     \
        asm volatile("cp.async.commit_group;" ::: "memory");                  \
    } while (0)

    ISSUE(0);

    const uint32_t aLane = (uint32_t)((wm * 64 + (L & 15)) * 80 + ((L >> 4) << 4));
    const uint32_t bRow  = (uint32_t)(L & 15);
    const uint32_t bSwzX = (uint32_t)(L & 7);
    const uint32_t bUL   = (uint32_t)(wn * 8 + (L >> 4));

    for (int kb = 0; kb < KB; kb++) {
        const uint32_t stg = sb + (uint32_t)(kb & 1) * STG;
        asm volatile("cp.async.wait_group 0;" ::: "memory");
        __syncthreads();
        if (kb + 1 < KB) ISSUE(kb + 1);

        #pragma unroll
        for (int ks = 0; ks < 2; ks++) {
            uint32_t ah[4][4], al[4][4];
            #pragma unroll
            for (int mt = 0; mt < 4; mt++) {
                uint32_t off = aLane + (uint32_t)(mt * 16 * 80 + ks * 32);
                ldsm4(ah[mt], stg + off);
                ldsm4(al[mt], stg + 10240 + off);
            }
            #pragma unroll
            for (int nj = 0; nj < 8; nj += 2) {
                uint32_t bh[4], bl[4];
                uint32_t off = (uint32_t)(ks * 16 + bRow) * 256
                             + (((bUL + nj) ^ bSwzX) << 4);
                ldsm4t(bh, stg + 20480 + off);
                ldsm4t(bl, stg + 28672 + off);
                #pragma unroll
                for (int mt = 0; mt < 4; mt++) {
                    mma16816(acc[mt][nj],   ah[mt], bh[0], bh[1]);
                    mma16816(acc[mt][nj+1], ah[mt], bh[2], bh[3]);
                    mma16816(acc[mt][nj],   ah[mt], bl[0], bl[1]);
                    mma16816(acc[mt][nj+1], ah[mt], bl[2], bl[3]);
                    mma16816(acc[mt][nj],   al[mt], bh[0], bh[1]);
                    mma16816(acc[mt][nj+1], al[mt], bh[2], bh[3]);
                }
            }
        }
        __syncthreads();
    }
    #undef ISSUE

    const float* bias = J.bias;
    float* C = J.C;
    __nv_bfloat16 *Chi = J.Chi, *Clo = J.Clo;
    const float scale = J.scale;
    const int act = J.act;

    float* sOut = (float*)dsm;
    const int gid = L >> 2, tig = L & 3;
    #pragma unroll
    for (int h = 0; h < 2; h++) {
        if (wn == h) {
            #pragma unroll
            for (int mt = 0; mt < 4; mt++) {
                #pragma unroll
                for (int nt = 0; nt < 8; nt++) {
                    const int srow = wm * 64 + mt * 16 + gid;
                    const int scol = nt * 8 + tig * 2;
                    const int gc   = col0 + h * 64 + scol;
                    float b0v = bias[gc], b1v = bias[gc + 1];
                    float v0 = (acc[mt][nt][0] + b0v) * scale;
                    float v1 = (acc[mt][nt][1] + b1v) * scale;
                    float v2 = (acc[mt][nt][2] + b0v) * scale;
                    float v3 = (acc[mt][nt][3] + b1v) * scale;
                    if (act) {
                        v0 = 0.5f*v0*(1.f+erff(v0*0.70710678118654752f));
                        v1 = 0.5f*v1*(1.f+erff(v1*0.70710678118654752f));
                        v2 = 0.5f*v2*(1.f+erff(v2*0.70710678118654752f));
                        v3 = 0.5f*v3*(1.f+erff(v3*0.70710678118654752f));
                    }
                    sOut[srow * 68 + scol]       = v0;
                    sOut[srow * 68 + scol + 1]   = v1;
                    sOut[(srow+8) * 68 + scol]   = v2;
                    sOut[(srow+8) * 68 + scol+1] = v3;
                }
            }
        }
        __syncthreads();
        #pragma unroll
        for (int i = 0; i < 16; i++) {
            const int f   = tid + i * 128;
            const int row = f >> 4;
            const int c4  = (f & 15) * 4;
            float4 v = *(const float4*)(sOut + row * 68 + c4);
            const size_t gidx = (size_t)(row0 + row) * N + col0 + h * 64 + c4;
            if (C) *(float4*)(C + gidx) = v;
            if (Chi) {
                float hx = __bfloat162float(__float2bfloat16_rn(v.x));
                float hy = __bfloat162float(__float2bfloat16_rn(v.y));
                float hz = __bfloat162float(__float2bfloat16_rn(v.z));
                float hw = __bfloat162float(__float2bfloat16_rn(v.w));
                uint2 H = { packbf(hx, hy), packbf(hz, hw) };
                uint2 Lo = { packbf(v.x - hx, v.y - hy), packbf(v.z - hz, v.w - hw) };
                *(uint2*)(Chi + gidx) = H;
                *(uint2*)(Clo + gidx) = Lo;
            }
        }
        __syncthreads();
    }
}

// ================= HMMA flash attention =====================================
// 128 threads (4 warps), QT=64 (16 q-rows/warp), kt tiles of 64.
// smem bytes: qh 0, ql 8192, kh 16384, kl 24576, vh 32768, vl 40960, msk 49152
#define ATT_SMEM (49152 + 256)

__global__ __launch_bounds__(128, 2)
void attn_hmma(const __nv_bfloat16* __restrict__ Qh, const __nv_bfloat16* __restrict__ Ql,
               const __nv_bfloat16* __restrict__ Kh, const __nv_bfloat16* __restrict__ Kl,
               const __nv_bfloat16* __restrict__ Vh, const __nv_bfloat16* __restrict__ Vl,
               const int* __restrict__ mask,
               __nv_bfloat16* __restrict__ Ohi, __nv_bfloat16* __restrict__ Olo)
{
    extern __shared__ char sm[];
    const uint32_t sb = smem_u32(sm);
    float* msk_s = (float*)(sm + 49152);
    const int tid = threadIdx.x, w = tid >> 5, L = tid & 31;
    const int qt = blockIdx.x, hh = blockIdx.y, b = blockIdx.z;
    const size_t base = (size_t)b * SEQ * DMODEL + (size_t)hh * DH;

    // ---- load Q tile (64x64 bf16 hi/lo) swizzled ----
    {
        const __nv_bfloat16* qh = Qh + base + (size_t)(qt * 64) * DMODEL;
        const __nv_bfloat16* ql = Ql + base + (size_t)(qt * 64) * DMODEL;
        #pragma unroll
        for (int it = 0; it < 4; it++) {
            int u = tid + it * 128;
            int r = u >> 3, c = u & 7;
            uint32_t off = (uint32_t)(r * 128 + ((c ^ (r & 7)) << 4));
            *(uint4*)(sm + off)        = *(const uint4*)(qh + (size_t)r * DMODEL + c * 8);
            *(uint4*)(sm + 8192 + off) = *(const uint4*)(ql + (size_t)r * DMODEL + c * 8);
        }
    }

    float m0 = -1e30f, m1 = -1e30f, l0 = 0.f, l1 = 0.f;
    float o[8][4];
    #pragma unroll
    for (int f = 0; f < 8; f++)
        #pragma unroll
        for (int t = 0; t < 4; t++) o[f][t] = 0.f;

    for (int kt = 0; kt < SEQ / 64; kt++) {
        __syncthreads();
        {
            const size_t kb = base + (size_t)(kt * 64) * DMODEL;
            #pragma unroll
            for (int it = 0; it < 4; it++) {
                int u = tid + it * 128;
                int r = u >> 3, c = u & 7;
                uint32_t off = (uint32_t)(r * 128 + ((c ^ (r & 7)) << 4));
                size_t g = kb + (size_t)r * DMODEL + c * 8;
                *(uint4*)(sm + 16384 + off) = *(const uint4*)(Kh + g);
                *(uint4*)(sm + 24576 + off) = *(const uint4*)(Kl + g);
                *(uint4*)(sm + 32768 + off) = *(const uint4*)(Vh + g);
                *(uint4*)(sm + 40960 + off) = *(const uint4*)(Vl + g);
            }
            if (tid < 64) msk_s[tid] = (float)mask[b * SEQ + kt * 64 + tid];
        }
        __syncthreads();

        // ---- S = Q @ K^T (3-term split) ----
        float s[8][4];
        #pragma unroll
        for (int f = 0; f < 8; f++)
            #pragma unroll
            for (int t = 0; t < 4; t++) s[f][t] = 0.f;

        #pragma unroll
        for (int ks = 0; ks < 4; ks++) {
            const int qrow = w * 16 + (L & 15);
            const uint32_t qoff = (uint32_t)(qrow * 128
                                  + (((ks * 2 + (L >> 4)) ^ (qrow & 7)) << 4));
            uint32_t qhf[4], qlf[4];
            ldsm4(qhf, sb + qoff);
            ldsm4(qlf, sb + 8192 + qoff);
            #pragma unroll
            for (int nj = 0; nj < 4; nj++) {
                const int krow = nj * 16 + (L & 7) + ((L >> 4) << 3);
                const uint32_t koff = (uint32_t)(krow * 128
                                      + (((ks * 2 + ((L >> 3) & 1)) ^ (krow & 7)) << 4));
                uint32_t khf[4], klf[4];
                ldsm4(khf, sb + 16384 + koff);
                ldsm4(klf, sb + 24576 + koff);
                mma16816(s[2*nj],   qhf, khf[0], khf[1]);
                mma16816(s[2*nj+1], qhf, khf[2], khf[3]);
                mma16816(s[2*nj],   qhf, klf[0], klf[1]);
                mma16816(s[2*nj+1], qhf, klf[2], klf[3]);
                mma16816(s[2*nj],   qlf, khf[0], khf[1]);
                mma16816(s[2*nj+1], qlf, khf[2], khf[3]);
            }
        }

        // ---- mask ----
        #pragma unroll
        for (int f = 0; f < 8; f++) {
            float mk0 = msk_s[f * 8 + 2 * (L & 3)];
            float mk1 = msk_s[f * 8 + 2 * (L & 3) + 1];
            if (mk0 == 0.f) { s[f][0] = -1e9f; s[f][2] = -1e9f; }
            if (mk1 == 0.f) { s[f][1] = -1e9f; s[f][3] = -1e9f; }
        }

        // ---- online softmax (rows L>>2 and L>>2 + 8; reduce over 4-lane group) ----
        float mx0 = -1e30f, mx1 = -1e30f;
        #pragma unroll
        for (int f = 0; f < 8; f++) {
            mx0 = fmaxf(mx0, fmaxf(s[f][0], s[f][1]));
            mx1 = fmaxf(mx1, fmaxf(s[f][2], s[f][3]));
        }
        #pragma unroll
        for (int ofs = 1; ofs <= 2; ofs <<= 1) {
            mx0 = fmaxf(mx0, __shfl_xor_sync(0xffffffffu, mx0, ofs, 4));
            mx1 = fmaxf(mx1, __shfl_xor_sync(0xffffffffu, mx1, ofs, 4));
        }
        float mn0 = fmaxf(m0, mx0), mn1 = fmaxf(m1, mx1);
        float al0 = __expf(m0 - mn0), al1 = __expf(m1 - mn1);
        m0 = mn0; m1 = mn1;
        float sum0 = 0.f, sum1 = 0.f;
        #pragma unroll
        for (int f = 0; f < 8; f++) {
            s[f][0] = __expf(s[f][0] - mn0); sum0 += s[f][0];
            s[f][1] = __expf(s[f][1] - mn0); sum0 += s[f][1];
            s[f][2] = __expf(s[f][2] - mn1); sum1 += s[f][2];
            s[f][3] = __expf(s[f][3] - mn1); sum1 += s[f][3];
        }
        #pragma unroll
        for (int ofs = 1; ofs <= 2; ofs <<= 1) {
            sum0 += __shfl_xor_sync(0xffffffffu, sum0, ofs, 4);
            sum1 += __shfl_xor_sync(0xffffffffu, sum1, ofs, 4);
        }
        l0 = l0 * al0 + sum0;
        l1 = l1 * al1 + sum1;
        #pragma unroll
        for (int f = 0; f < 8; f++) {
            o[f][0] *= al0; o[f][1] *= al0; o[f][2] *= al1; o[f][3] *= al1;
        }

        // ---- PV: acc += P @ V (3-term split) ----
        #pragma unroll
        for (int s4 = 0; s4 < 4; s4++) {
            uint32_t ph[4], pl[4];
            {
                float p00 = s[2*s4][0],   p01 = s[2*s4][1];
                float p02 = s[2*s4][2],   p03 = s[2*s4][3];
                float p10 = s[2*s4+1][0], p11 = s[2*s4+1][1];
                float p12 = s[2*s4+1][2], p13 = s[2*s4+1][3];
                ph[0] = packbf(p00, p01); ph[1] = packbf(p02, p03);
                ph[2] = packbf(p10, p11); ph[3] = packbf(p12, p13);
                pl[0] = packbf(p00 - __bfloat162float(__float2bfloat16_rn(p00)),
                               p01 - __bfloat162float(__float2bfloat16_rn(p01)));
                pl[1] = packbf(p02 - __bfloat162float(__float2bfloat16_rn(p02)),
                               p03 - __bfloat162float(__float2bfloat16_rn(p03)));
                pl[2] = packbf(p10 - __bfloat162float(__float2bfloat16_rn(p10)),
                               p11 - __bfloat162float(__float2bfloat16_rn(p11)));
                pl[3] = packbf(p12 - __bfloat162float(__float2bfloat16_rn(p12)),
                               p13 - __bfloat162float(__float2bfloat16_rn(p13)));
            }
            #pragma unroll
            for (int dj = 0; dj < 4; dj++) {
                const int vrow = s4 * 16 + (L & 15);
                const uint32_t voff = (uint32_t)(vrow * 128
                                      + (((dj * 2 + (L >> 4)) ^ (vrow & 7)) << 4));
                uint32_t vhf[4], vlf[4];
                ldsm4t(vhf, sb + 32768 + voff);
                ldsm4t(vlf, sb + 40960 + voff);
                mma16816(o[2*dj],   ph, vhf[0], vhf[1]);
                mma16816(o[2*dj+1], ph, vhf[2], vhf[3]);
                mma16816(o[2*dj],   ph, vlf[0], vlf[1]);
                mma16816(o[2*dj+1], ph, vlf[2], vlf[3]);
                mma16816(o[2*dj],   pl, vhf[0], vhf[1]);
                mma16816(o[2*dj+1], pl, vhf[2], vhf[3]);
            }
        }
    }

    // ---- output: bf16 hi/lo, 4B packed stores ----
    const float inv0 = 1.f / l0, inv1 = 1.f / l1;
    const int r0 = qt * 64 + w * 16 + (L >> 2);
    #pragma unroll
    for (int f = 0; f < 8; f++) {
        const int c = f * 8 + 2 * (L & 3);
        const size_t i0 = base + (size_t)r0 * DMODEL + c;
        const size_t i1 = base + (size_t)(r0 + 8) * DMODEL + c;
        float v0 = o[f][0] * inv0, v1 = o[f][1] * inv0;
        float v2 = o[f][2] * inv1, v3 = o[f][3] * inv1;
        float h0 = __bfloat162float(__float2bfloat16_rn(v0));
        float h1 = __bfloat162float(__float2bfloat16_rn(v1));
        float h2v = __bfloat162float(__float2bfloat16_rn(v2));
        float h3 = __bfloat162float(__float2bfloat16_rn(v3));
        *(uint32_t*)(Ohi + i0) = packbf(v0, v1);
        *(uint32_t*)(Olo + i0) = packbf(v0 - h0, v1 - h1);
        *(uint32_t*)(Ohi + i1) = packbf(v2, v3);
        *(uint32_t*)(Olo + i1) = packbf(v2 - h2v, v3 - h3);
    }
}

// ---------------- residual add + LayerNorm (+ optional bf16 hi/lo out) ------
__device__ __forceinline__ float blockReduceSum(float val)
{
    __shared__ float red[8];
    __syncthreads();
    int lane = threadIdx.x & 31, wid = threadIdx.x >> 5;
    #pragma unroll
    for (int o = 16; o > 0; o >>= 1) val += __shfl_down_sync(0xffffffffu, val, o);
    if (lane == 0) red[wid] = val;
    __syncthreads();
    if (wid == 0) {
        val = (lane < 8) ? red[lane] : 0.f;
        #pragma unroll
        for (int o = 4; o > 0; o >>= 1) val += __shfl_down_sync(0xffffffffu, val, o);
        if (lane == 0) red[0] = val;
    }
    __syncthreads();
    return red[0];
}

__global__ __launch_bounds__(256)
void add_ln_kernel(const float* __restrict__ a, const float* __restrict__ res,
                   const float* __restrict__ g, const float* __restrict__ bt,
                   float* __restrict__ out,
                   __nv_bfloat16* __restrict__ ohi, __nv_bfloat16* __restrict__ olo)
{
    const int row = blockIdx.x;
    const int tid = threadIdx.x;
    float v[3];
    float sum = 0.f;
    #pragma unroll
    for (int i = 0; i < 3; i++) {
        int c = tid + i * 256;
        v[i] = a[(size_t)row * DMODEL + c] + res[(size_t)row * DMODEL + c];
        sum += v[i];
    }
    sum = blockReduceSum(sum);
    const float mu = sum * (1.f / DMODEL);
    float s2 = 0.f;
    #pragma unroll
    for (int i = 0; i < 3; i++) { float d = v[i] - mu; s2 += d * d; }
    s2 = blockReduceSum(s2);
    const float rs = rsqrtf(s2 * (1.f / DMODEL) + 1e-12f);
    #pragma unroll
    for (int i = 0; i < 3; i++) {
        int c = tid + i * 256;
        float val = (v[i] - mu) * rs * g[c] + bt[c];
        out[(size_t)row * DMODEL + c] = val;
        if (ohi) {
            float hf = __bfloat162float(__float2bfloat16_rn(val));
            ohi[(size_t)row * DMODEL + c] = __float2bfloat16_rn(val);
            olo[(size_t)row * DMODEL + c] = __float2bfloat16_rn(val - hf);
        }
    }
}

// ---------------- driver -----------------------------------------------------
extern "C" void kernel_launch(void* const* d_in, const int* in_sizes, int n_in,
                              void* d_out, int out_size)
{
    const float* x     = (const float*)d_in[0];
    const int*   amask = (const int*)  d_in[1];
    const float* Wq    = (const float*)d_in[2];
    const float* bq    = (const float*)d_in[3];
    const float* Wk    = (const float*)d_in[4];
    const float* bk    = (const float*)d_in[5];
    const float* Wv    = (const float*)d_in[6];
    const float* bv    = (const float*)d_in[7];
    const float* Wo    = (const float*)d_in[8];
    const float* bo    = (const float*)d_in[9];
    const float* ln1g  = (const float*)d_in[10];
    const float* ln1b  = (const float*)d_in[11];
    const float* W1    = (const float*)d_in[12];
    const float* b1    = (const float*)d_in[13];
    const float* W2    = (const float*)d_in[14];
    const float* b2    = (const float*)d_in[15];
    const float* ln2g  = (const float*)d_in[16];
    const float* ln2b  = (const float*)d_in[17];
    float* out = (float*)d_out;

    float *h, *h2, *tmp;
    __nv_bfloat16 *whi, *wlo, *ahi, *alo, *chi, *clo, *fhi, *flo;
    __nv_bfloat16 *qhi, *qlo, *khi, *klo, *vhi, *vlo;
    cudaGetSymbolAddress((void**)&h,   g_h);
    cudaGetSymbolAddress((void**)&h2,  g_h2);
    cudaGetSymbolAddress((void**)&tmp, g_tmp);
    cudaGetSymbolAddress((void**)&whi, g_whi);
    cudaGetSymbolAddress((void**)&wlo, g_wlo);
    cudaGetSymbolAddress((void**)&ahi, g_ahi);
    cudaGetSymbolAddress((void**)&alo, g_alo);
    cudaGetSymbolAddress((void**)&qhi, g_qhi);
    cudaGetSymbolAddress((void**)&qlo, g_qlo);
    cudaGetSymbolAddress((void**)&khi, g_khi);
    cudaGetSymbolAddress((void**)&klo, g_klo);
    cudaGetSymbolAddress((void**)&vhi, g_vhi);
    cudaGetSymbolAddress((void**)&vlo, g_vlo);
    cudaGetSymbolAddress((void**)&chi, g_chi);
    cudaGetSymbolAddress((void**)&clo, g_clo);
    cudaGetSymbolAddress((void**)&fhi, g_fhi);
    cudaGetSymbolAddress((void**)&flo, g_flo);

    cudaFuncSetAttribute(hmma_gemm, cudaFuncAttributeMaxDynamicSharedMemorySize, GEMM_SMEM);
    cudaFuncSetAttribute(attn_hmma, cudaFuncAttributeMaxDynamicSharedMemorySize, ATT_SMEM);

    const int nDD4 = SZ_DD / 4;
    const int nDF4 = SZ_DF / 4;
    f2bf<<<nDD4/256, 256>>>((const float4*)Wq, (uint2*)(whi+OQ),  (uint2*)(wlo+OQ),  nDD4);
    f2bf<<<nDD4/256, 256>>>((const float4*)Wk, (uint2*)(whi+OKk), (uint2*)(wlo+OKk), nDD4);
    f2bf<<<nDD4/256, 256>>>((const float4*)Wv, (uint2*)(whi+OV),  (uint2*)(wlo+OV),  nDD4);
    f2bf<<<nDD4/256, 256>>>((const float4*)Wo, (uint2*)(whi+OO),  (uint2*)(wlo+OO),  nDD4);
    f2bf<<<nDF4/256, 256>>>((const float4*)W1, (uint2*)(whi+O1),  (uint2*)(wlo+O1),  nDF4);
    f2bf<<<nDF4/256, 256>>>((const float4*)W2, (uint2*)(whi+O2),  (uint2*)(wlo+O2),  nDF4);

    const int nAct4 = NTOK * DMODEL / 4;
    const dim3 gQKV(DMODEL / 128, NTOK / 128, 3);
    const dim3 gD(DMODEL / 128, NTOK / 128, 1);
    const dim3 gF(FFD    / 128, NTOK / 128, 1);
    const dim3 gA(SEQ / 64, NH, BATCH);

    f2bf<<<nAct4/256, 256>>>((const float4*)x, (uint2*)ahi, (uint2*)alo, nAct4);

    for (int i = 0; i < NL; i++) {
        const float* cur = (i == 0) ? x : h;
        const size_t wdd = (size_t)i * DMODEL * DMODEL;
        const size_t wdf = (size_t)i * DMODEL * FFD;

        GemmParams pq = {};
        pq.job[0] = { whi+OQ+wdd,  wlo+OQ+wdd,  bq + i*DMODEL, 0, qhi, qlo, 0.125f, 0 };
        pq.job[1] = { whi+OKk+wdd, wlo+OKk+wdd, bk + i*DMODEL, 0, khi, klo, 1.f,    0 };
        pq.job[2] = { whi+OV+wdd,  wlo+OV+wdd,  bv + i*DMODEL, 0, vhi, vlo, 1.f,    0 };
        hmma_gemm<<<gQKV, 128, GEMM_SMEM>>>(ahi, alo, pq, NTOK, DMODEL, DMODEL);

        attn_hmma<<<gA, 128, ATT_SMEM>>>(qhi, qlo, khi, klo, vhi, vlo, amask, chi, clo);

        GemmParams po = {};
        po.job[0] = { whi+OO+wdd, wlo+OO+wdd, bo + i*DMODEL, tmp, 0, 0, 1.f, 0 };
        hmma_gemm<<<gD, 128, GEMM_SMEM>>>(chi, clo, po, NTOK, DMODEL, DMODEL);

        add_ln_kernel<<<NTOK, 256>>>(tmp, cur, ln1g + i*DMODEL, ln1b + i*DMODEL,
                                     h2, ahi, alo);

        GemmParams p1 = {};
        p1.job[0] = { whi+O1+wdf, wlo+O1+wdf, b1 + i*FFD, 0, fhi, flo, 1.f, 1 };
        hmma_gemm<<<gF, 128, GEMM_SMEM>>>(ahi, alo, p1, NTOK, FFD, DMODEL);

        GemmParams p2 = {};
        p2.job[0] = { whi+O2+wdf, wlo+O2+wdf, b2 + i*DMODEL, tmp, 0, 0, 1.f, 0 };
        hmma_gemm<<<gD, 128, GEMM_SMEM>>>(fhi, flo, p2, NTOK, DMODEL, FFD);

        float* dst = (i == NL - 1) ? out : h;
        add_ln_kernel<<<NTOK, 256>>>(tmp, h2, ln2g + i*DMODEL, ln2b + i*DMODEL,
                                     dst, (i < NL-1) ? ahi : 0, (i < NL-1) ? alo : 0);
    }
}

// round 8
// speedup vs baseline: 3.6300x; 1.1000x over previous
#include <cuda_runtime.h>
#include <cuda_bf16.h>
#include <math.h>
#include <stdint.h>

#define DMODEL 768
#define FFD    3072
#define NL     6
#define NH     12
#define DH     64
#define SEQ    512
#define BATCH  8
#define NTOK   (BATCH*SEQ)   // 4096

#define SZ_DD  (NL*DMODEL*DMODEL)
#define SZ_DF  (NL*DMODEL*FFD)
#define OQ 0
#define OKk (SZ_DD)
#define OV  (2*SZ_DD)
#define OO  (3*SZ_DD)
#define O1  (4*SZ_DD)
#define O2  (4*SZ_DD + SZ_DF)
#define WTOT (4*SZ_DD + 2*SZ_DF)

// ---------------- scratch (static device globals; no runtime allocation) ----
__device__ float g_h  [NTOK*DMODEL];
__device__ float g_h2 [NTOK*DMODEL];
__device__ float g_tmp[NTOK*DMODEL];
__device__ __nv_bfloat16 g_whi[WTOT];
__device__ __nv_bfloat16 g_wlo[WTOT];
__device__ __nv_bfloat16 g_ahi[NTOK*DMODEL];
__device__ __nv_bfloat16 g_alo[NTOK*DMODEL];
__device__ __nv_bfloat16 g_qhi[NTOK*DMODEL];
__device__ __nv_bfloat16 g_qlo[NTOK*DMODEL];
__device__ __nv_bfloat16 g_khi[NTOK*DMODEL];
__device__ __nv_bfloat16 g_klo[NTOK*DMODEL];
__device__ __nv_bfloat16 g_vhi[NTOK*DMODEL];
__device__ __nv_bfloat16 g_vlo[NTOK*DMODEL];
__device__ __nv_bfloat16 g_chi[NTOK*DMODEL];
__device__ __nv_bfloat16 g_clo[NTOK*DMODEL];
__device__ __nv_bfloat16 g_fhi[NTOK*FFD];
__device__ __nv_bfloat16 g_flo[NTOK*FFD];

// ================= helpers ==================================================
__device__ __forceinline__ uint32_t smem_u32(const void* p) {
    uint32_t a;
    asm("{ .reg .u64 t; cvta.to.shared.u64 t, %1; cvt.u32.u64 %0, t; }"
        : "=r"(a) : "l"(p));
    return a;
}
__device__ __forceinline__ uint32_t packbf(float x, float y) {
    __nv_bfloat162 t = __floats2bfloat162_rn(x, y);
    return *(uint32_t*)&t;
}
__device__ __forceinline__ void cpa16(uint32_t dst, const void* src) {
    asm volatile("cp.async.cg.shared.global [%0], [%1], 16;"
                 :: "r"(dst), "l"(src) : "memory");
}
__device__ __forceinline__ void ldsm4(uint32_t* r, uint32_t addr) {
    asm volatile("ldmatrix.sync.aligned.m8n8.x4.shared.b16 {%0,%1,%2,%3}, [%4];"
                 : "=r"(r[0]), "=r"(r[1]), "=r"(r[2]), "=r"(r[3]) : "r"(addr));
}
__device__ __forceinline__ void ldsm4t(uint32_t* r, uint32_t addr) {
    asm volatile("ldmatrix.sync.aligned.m8n8.x4.trans.shared.b16 {%0,%1,%2,%3}, [%4];"
                 : "=r"(r[0]), "=r"(r[1]), "=r"(r[2]), "=r"(r[3]) : "r"(addr));
}
__device__ __forceinline__ void mma16816(float* d, const uint32_t* a,
                                         uint32_t b0, uint32_t b1) {
    asm volatile(
        "mma.sync.aligned.m16n8k16.row.col.f32.bf16.bf16.f32 "
        "{%0,%1,%2,%3}, {%4,%5,%6,%7}, {%8,%9}, {%0,%1,%2,%3};"
        : "+f"(d[0]), "+f"(d[1]), "+f"(d[2]), "+f"(d[3])
        : "r"(a[0]), "r"(a[1]), "r"(a[2]), "r"(a[3]), "r"(b0), "r"(b1));
}

// ================= fp32 -> bf16 hi/lo split conversion ======================
__global__ __launch_bounds__(256)
void f2bf(const float4* __restrict__ in, uint2* __restrict__ hi,
          uint2* __restrict__ lo, int n4)
{
    int i = blockIdx.x * 256 + threadIdx.x;
    if (i >= n4) return;
    float4 f = in[i];
    float hx = __bfloat162float(__float2bfloat16_rn(f.x));
    float hy = __bfloat162float(__float2bfloat16_rn(f.y));
    float hz = __bfloat162float(__float2bfloat16_rn(f.z));
    float hw = __bfloat162float(__float2bfloat16_rn(f.w));
    uint2 H = { packbf(hx, hy), packbf(hz, hw) };
    uint2 Lo = { packbf(f.x - hx, f.y - hy), packbf(f.z - hz, f.w - hw) };
    hi[i] = H;
    lo[i] = Lo;
}

// ================= split-bf16 HMMA GEMM (templated M-tile) ==================
// MT = m-subtiles per warp: CTA tile = (MT*32) x 128, 4 warps, BK=32,
// 2-stage cp.async. MT=4 -> 2 CTA/SM; MT=2 -> 3 CTA/SM.
struct GemmJob {
    const __nv_bfloat16 *Bh, *Bl;
    const float* bias;
    float* C;
    __nv_bfloat16 *Chi, *Clo;
    float scale;
    int act;
};
struct GemmParams { GemmJob job[3]; };

template <int MT>
__global__ __launch_bounds__(128, (MT == 2) ? 3 : 2)
void hmma_gemm(const __nv_bfloat16* __restrict__ Ahi,
               const __nv_bfloat16* __restrict__ Alo,
               GemmParams P, int M, int N, int K)
{
    constexpr int ASEC = MT * 2560;            // bytes per A (hi or lo) section
    constexpr int BOFF = 2 * ASEC;             // B hi offset
    constexpr int STG  = 2 * ASEC + 16384;     // bytes per stage
    constexpr int CTAM = MT * 32;

    extern __shared__ char dsm[];
    const GemmJob& J = P.job[blockIdx.z];
    const __nv_bfloat16* __restrict__ Bhi = J.Bh;
    const __nv_bfloat16* __restrict__ Blo = J.Bl;

    const uint32_t sb = smem_u32(dsm);
    const int tid = threadIdx.x;
    const int wid = tid >> 5, L = tid & 31;
    const int wm = wid & 1, wn = wid >> 1;
    const int row0 = blockIdx.y * CTAM, col0 = blockIdx.x * 128;

    float acc[MT][8][4];
    #pragma unroll
    for (int i = 0; i < MT; i++)
        #pragma unroll
        for (int j = 0; j < 8; j++)
            #pragma unroll
            for (int t = 0; t < 4; t++) acc[i][j][t] = 0.f;

    const int aR = tid >> 2, aU = tid & 3;
    const int bR = tid >> 4, bU = tid & 15;
    const uint32_t aDst = (uint32_t)(aR * 80 + aU * 16);
    const uint32_t bDst = (uint32_t)(bR * 256 + ((bU ^ (bR & 7)) << 4));

    const __nv_bfloat16* aHb = Ahi + (size_t)(row0 + aR) * K + aU * 8;
    const __nv_bfloat16* aLb = Alo + (size_t)(row0 + aR) * K + aU * 8;
    const __nv_bfloat16* bHb = Bhi + (size_t)bR * N + col0 + bU * 8;
    const __nv_bfloat16* bLb = Blo + (size_t)bR * N + col0 + bU * 8;

    const int KB = K >> 5;

    #define ISSUE(kb) do {                                                    \
        const uint32_t stg_ = sb + (uint32_t)((kb) & 1) * STG;                \
        const int k0_ = (kb) * 32;                                            \
        _Pragma("unroll")                                                     \
        for (int p = 0; p < MT; p++) {                                        \
            cpa16(stg_ + aDst + p * 2560,        aHb + k0_ + (size_t)(p*32) * K); \
            cpa16(stg_ + ASEC + aDst + p * 2560, aLb + k0_ + (size_t)(p*32) * K); \
        }                                                                     \
        _Pragma("unroll")                                                     \
        for (int p = 0; p < 4; p++) {                                         \
            cpa16(stg_ + BOFF + bDst + p * 2048,        bHb + (size_t)(k0_ + p*8) * N); \
            cpa16(stg_ + BOFF + 8192 + bDst + p * 2048, bLb + (size_t)(k0_ + p*8) * N); \
        }                                                                     \
        asm volatile("cp.async.commit_group;" ::: "memory");                  \
    } while (0)

    ISSUE(0);

    const uint32_t aLane = (uint32_t)((wm * (MT*16) + (L & 15)) * 80 + ((L >> 4) << 4));
    const uint32_t bRow  = (uint32_t)(L & 15);
    const uint32_t bSwzX = (uint32_t)(L & 7);
    const uint32_t bUL   = (uint32_t)(wn * 8 + (L >> 4));

    for (int kb = 0; kb < KB; kb++) {
        const uint32_t stg = sb + (uint32_t)(kb & 1) * STG;
        asm volatile("cp.async.wait_group 0;" ::: "memory");
        __syncthreads();
        if (kb + 1 < KB) ISSUE(kb + 1);

        #pragma unroll
        for (int ks = 0; ks < 2; ks++) {
            uint32_t ah[MT][4], al[MT][4];
            #pragma unroll
            for (int mt = 0; mt < MT; mt++) {
                uint32_t off = aLane + (uint32_t)(mt * 16 * 80 + ks * 32);
                ldsm4(ah[mt], stg + off);
                ldsm4(al[mt], stg + ASEC + off);
            }
            #pragma unroll
            for (int nj = 0; nj < 8; nj += 2) {
                uint32_t bh[4], bl[4];
                uint32_t off = (uint32_t)(ks * 16 + bRow) * 256
                             + (((bUL + nj) ^ bSwzX) << 4);
                ldsm4t(bh, stg + BOFF + off);
                ldsm4t(bl, stg + BOFF + 8192 + off);
                #pragma unroll
                for (int mt = 0; mt < MT; mt++) {
                    mma16816(acc[mt][nj],   ah[mt], bh[0], bh[1]);
                    mma16816(acc[mt][nj+1], ah[mt], bh[2], bh[3]);
                    mma16816(acc[mt][nj],   ah[mt], bl[0], bl[1]);
                    mma16816(acc[mt][nj+1], ah[mt], bl[2], bl[3]);
                    mma16816(acc[mt][nj],   al[mt], bh[0], bh[1]);
                    mma16816(acc[mt][nj+1], al[mt], bh[2], bh[3]);
                }
            }
        }
        __syncthreads();
    }
    #undef ISSUE

    const float* bias = J.bias;
    float* C = J.C;
    __nv_bfloat16 *Chi = J.Chi, *Clo = J.Clo;
    const float scale = J.scale;
    const int act = J.act;

    float* sOut = (float*)dsm;               // CTAM x 68 fp32
    const int gid = L >> 2, tig = L & 3;
    #pragma unroll
    for (int h = 0; h < 2; h++) {
        if (wn == h) {
            #pragma unroll
            for (int mt = 0; mt < MT; mt++) {
                #pragma unroll
                for (int nt = 0; nt < 8; nt++) {
                    const int srow = wm * (MT*16) + mt * 16 + gid;
                    const int scol = nt * 8 + tig * 2;
                    const int gc   = col0 + h * 64 + scol;
                    float b0v = bias[gc], b1v = bias[gc + 1];
                    float v0 = (acc[mt][nt][0] + b0v) * scale;
                    float v1 = (acc[mt][nt][1] + b1v) * scale;
                    float v2 = (acc[mt][nt][2] + b0v) * scale;
                    float v3 = (acc[mt][nt][3] + b1v) * scale;
                    if (act) {
                        v0 = 0.5f*v0*(1.f+erff(v0*0.70710678118654752f));
                        v1 = 0.5f*v1*(1.f+erff(v1*0.70710678118654752f));
                        v2 = 0.5f*v2*(1.f+erff(v2*0.70710678118654752f));
                        v3 = 0.5f*v3*(1.f+erff(v3*0.70710678118654752f));
                    }
                    sOut[srow * 68 + scol]       = v0;
                    sOut[srow * 68 + scol + 1]   = v1;
                    sOut[(srow+8) * 68 + scol]   = v2;
                    sOut[(srow+8) * 68 + scol+1] = v3;
                }
            }
        }
        __syncthreads();
        #pragma unroll
        for (int i = 0; i < MT*4; i++) {
            const int f   = tid + i * 128;
            const int row = f >> 4;
            const int c4  = (f & 15) * 4;
            float4 v = *(const float4*)(sOut + row * 68 + c4);
            const size_t gidx = (size_t)(row0 + row) * N + col0 + h * 64 + c4;
            if (C) *(float4*)(C + gidx) = v;
            if (Chi) {
                float hx = __bfloat162float(__float2bfloat16_rn(v.x));
                float hy = __bfloat162float(__float2bfloat16_rn(v.y));
                float hz = __bfloat162float(__float2bfloat16_rn(v.z));
                float hw = __bfloat162float(__float2bfloat16_rn(v.w));
                uint2 H = { packbf(hx, hy), packbf(hz, hw) };
                uint2 Lo = { packbf(v.x - hx, v.y - hy), packbf(v.z - hz, v.w - hw) };
                *(uint2*)(Chi + gidx) = H;
                *(uint2*)(Clo + gidx) = Lo;
            }
        }
        __syncthreads();
    }
}

#define GEMM_SMEM4 (2*(4*2560*2 + 16384))   // 73728
#define GEMM_SMEM2 (2*(2*2560*2 + 16384))   // 53248

// ================= HMMA flash attention =====================================
#define ATT_SMEM (49152 + 256)

__global__ __launch_bounds__(128, 2)
void attn_hmma(const __nv_bfloat16* __restrict__ Qh, const __nv_bfloat16* __restrict__ Ql,
               const __nv_bfloat16* __restrict__ Kh, const __nv_bfloat16* __restrict__ Kl,
               const __nv_bfloat16* __restrict__ Vh, const __nv_bfloat16* __restrict__ Vl,
               const int* __restrict__ mask,
               __nv_bfloat16* __restrict__ Ohi, __nv_bfloat16* __restrict__ Olo)
{
    extern __shared__ char sm[];
    const uint32_t sb = smem_u32(sm);
    float* msk_s = (float*)(sm + 49152);
    const int tid = threadIdx.x, w = tid >> 5, L = tid & 31;
    const int qt = blockIdx.x, hh = blockIdx.y, b = blockIdx.z;
    const size_t base = (size_t)b * SEQ * DMODEL + (size_t)hh * DH;

    {
        const __nv_bfloat16* qh = Qh + base + (size_t)(qt * 64) * DMODEL;
        const __nv_bfloat16* ql = Ql + base + (size_t)(qt * 64) * DMODEL;
        #pragma unroll
        for (int it = 0; it < 4; it++) {
            int u = tid + it * 128;
            int r = u >> 3, c = u & 7;
            uint32_t off = (uint32_t)(r * 128 + ((c ^ (r & 7)) << 4));
            *(uint4*)(sm + off)        = *(const uint4*)(qh + (size_t)r * DMODEL + c * 8);
            *(uint4*)(sm + 8192 + off) = *(const uint4*)(ql + (size_t)r * DMODEL + c * 8);
        }
    }

    float m0 = -1e30f, m1 = -1e30f, l0 = 0.f, l1 = 0.f;
    float o[8][4];
    #pragma unroll
    for (int f = 0; f < 8; f++)
        #pragma unroll
        for (int t = 0; t < 4; t++) o[f][t] = 0.f;

    for (int kt = 0; kt < SEQ / 64; kt++) {
        __syncthreads();
        {
            const size_t kb = base + (size_t)(kt * 64) * DMODEL;
            #pragma unroll
            for (int it = 0; it < 4; it++) {
                int u = tid + it * 128;
                int r = u >> 3, c = u & 7;
                uint32_t off = (uint32_t)(r * 128 + ((c ^ (r & 7)) << 4));
                size_t g = kb + (size_t)r * DMODEL + c * 8;
                *(uint4*)(sm + 16384 + off) = *(const uint4*)(Kh + g);
                *(uint4*)(sm + 24576 + off) = *(const uint4*)(Kl + g);
                *(uint4*)(sm + 32768 + off) = *(const uint4*)(Vh + g);
                *(uint4*)(sm + 40960 + off) = *(const uint4*)(Vl + g);
            }
            if (tid < 64) msk_s[tid] = (float)mask[b * SEQ + kt * 64 + tid];
        }
        __syncthreads();

        float s[8][4];
        #pragma unroll
        for (int f = 0; f < 8; f++)
            #pragma unroll
            for (int t = 0; t < 4; t++) s[f][t] = 0.f;

        #pragma unroll
        for (int ks = 0; ks < 4; ks++) {
            const int qrow = w * 16 + (L & 15);
            const uint32_t qoff = (uint32_t)(qrow * 128
                                  + (((ks * 2 + (L >> 4)) ^ (qrow & 7)) << 4));
            uint32_t qhf[4], qlf[4];
            ldsm4(qhf, sb + qoff);
            ldsm4(qlf, sb + 8192 + qoff);
            #pragma unroll
            for (int nj = 0; nj < 4; nj++) {
                const int krow = nj * 16 + (L & 7) + ((L >> 4) << 3);
                const uint32_t koff = (uint32_t)(krow * 128
                                      + (((ks * 2 + ((L >> 3) & 1)) ^ (krow & 7)) << 4));
                uint32_t khf[4], klf[4];
                ldsm4(khf, sb + 16384 + koff);
                ldsm4(klf, sb + 24576 + koff);
                mma16816(s[2*nj],   qhf, khf[0], khf[1]);
                mma16816(s[2*nj+1], qhf, khf[2], khf[3]);
                mma16816(s[2*nj],   qhf, klf[0], klf[1]);
                mma16816(s[2*nj+1], qhf, klf[2], klf[3]);
                mma16816(s[2*nj],   qlf, khf[0], khf[1]);
                mma16816(s[2*nj+1], qlf, khf[2], khf[3]);
            }
        }

        #pragma unroll
        for (int f = 0; f < 8; f++) {
            float mk0 = msk_s[f * 8 + 2 * (L & 3)];
            float mk1 = msk_s[f * 8 + 2 * (L & 3) + 1];
            if (mk0 == 0.f) { s[f][0] = -1e9f; s[f][2] = -1e9f; }
            if (mk1 == 0.f) { s[f][1] = -1e9f; s[f][3] = -1e9f; }
        }

        float mx0 = -1e30f, mx1 = -1e30f;
        #pragma unroll
        for (int f = 0; f < 8; f++) {
            mx0 = fmaxf(mx0, fmaxf(s[f][0], s[f][1]));
            mx1 = fmaxf(mx1, fmaxf(s[f][2], s[f][3]));
        }
        #pragma unroll
        for (int ofs = 1; ofs <= 2; ofs <<= 1) {
            mx0 = fmaxf(mx0, __shfl_xor_sync(0xffffffffu, mx0, ofs, 4));
            mx1 = fmaxf(mx1, __shfl_xor_sync(0xffffffffu, mx1, ofs, 4));
        }
        float mn0 = fmaxf(m0, mx0), mn1 = fmaxf(m1, mx1);
        float al0 = __expf(m0 - mn0), al1 = __expf(m1 - mn1);
        m0 = mn0; m1 = mn1;
        float sum0 = 0.f, sum1 = 0.f;
        #pragma unroll
        for (int f = 0; f < 8; f++) {
            s[f][0] = __expf(s[f][0] - mn0); sum0 += s[f][0];
            s[f][1] = __expf(s[f][1] - mn0); sum0 += s[f][1];
            s[f][2] = __expf(s[f][2] - mn1); sum1 += s[f][2];
            s[f][3] = __expf(s[f][3] - mn1); sum1 += s[f][3];
        }
        #pragma unroll
        for (int ofs = 1; ofs <= 2; ofs <<= 1) {
            sum0 += __shfl_xor_sync(0xffffffffu, sum0, ofs, 4);
            sum1 += __shfl_xor_sync(0xffffffffu, sum1, ofs, 4);
        }
        l0 = l0 * al0 + sum0;
        l1 = l1 * al1 + sum1;
        #pragma unroll
        for (int f = 0; f < 8; f++) {
            o[f][0] *= al0; o[f][1] *= al0; o[f][2] *= al1; o[f][3] *= al1;
        }

        #pragma unroll
        for (int s4 = 0; s4 < 4; s4++) {
            uint32_t ph[4], pl[4];
            {
                float p00 = s[2*s4][0],   p01 = s[2*s4][1];
                float p02 = s[2*s4][2],   p03 = s[2*s4][3];
                float p10 = s[2*s4+1][0], p11 = s[2*s4+1][1];
                float p12 = s[2*s4+1][2], p13 = s[2*s4+1][3];
                ph[0] = packbf(p00, p01); ph[1] = packbf(p02, p03);
                ph[2] = packbf(p10, p11); ph[3] = packbf(p12, p13);
                pl[0] = packbf(p00 - __bfloat162float(__float2bfloat16_rn(p00)),
                               p01 - __bfloat162float(__float2bfloat16_rn(p01)));
                pl[1] = packbf(p02 - __bfloat162float(__float2bfloat16_rn(p02)),
                               p03 - __bfloat162float(__float2bfloat16_rn(p03)));
                pl[2] = packbf(p10 - __bfloat162float(__float2bfloat16_rn(p10)),
                               p11 - __bfloat162float(__float2bfloat16_rn(p11)));
                pl[3] = packbf(p12 - __bfloat162float(__float2bfloat16_rn(p12)),
                               p13 - __bfloat162float(__float2bfloat16_rn(p13)));
            }
            #pragma unroll
            for (int dj = 0; dj < 4; dj++) {
                const int vrow = s4 * 16 + (L & 15);
                const uint32_t voff = (uint32_t)(vrow * 128
                                      + (((dj * 2 + (L >> 4)) ^ (vrow & 7)) << 4));
                uint32_t vhf[4], vlf[4];
                ldsm4t(vhf, sb + 32768 + voff);
                ldsm4t(vlf, sb + 40960 + voff);
                mma16816(o[2*dj],   ph, vhf[0], vhf[1]);
                mma16816(o[2*dj+1], ph, vhf[2], vhf[3]);
                mma16816(o[2*dj],   ph, vlf[0], vlf[1]);
                mma16816(o[2*dj+1], ph, vlf[2], vlf[3]);
                mma16816(o[2*dj],   pl, vhf[0], vhf[1]);
                mma16816(o[2*dj+1], pl, vhf[2], vhf[3]);
            }
        }
    }

    const float inv0 = 1.f / l0, inv1 = 1.f / l1;
    const int r0 = qt * 64 + w * 16 + (L >> 2);
    #pragma unroll
    for (int f = 0; f < 8; f++) {
        const int c = f * 8 + 2 * (L & 3);
        const size_t i0 = base + (size_t)r0 * DMODEL + c;
        const size_t i1 = base + (size_t)(r0 + 8) * DMODEL + c;
        float v0 = o[f][0] * inv0, v1 = o[f][1] * inv0;
        float v2 = o[f][2] * inv1, v3 = o[f][3] * inv1;
        float h0 = __bfloat162float(__float2bfloat16_rn(v0));
        float h1 = __bfloat162float(__float2bfloat16_rn(v1));
        float h2v = __bfloat162float(__float2bfloat16_rn(v2));
        float h3 = __bfloat162float(__float2bfloat16_rn(v3));
        *(uint32_t*)(Ohi + i0) = packbf(v0, v1);
        *(uint32_t*)(Olo + i0) = packbf(v0 - h0, v1 - h1);
        *(uint32_t*)(Ohi + i1) = packbf(v2, v3);
        *(uint32_t*)(Olo + i1) = packbf(v2 - h2v, v3 - h3);
    }
}

// ---------------- residual add + LayerNorm (+ optional bf16 hi/lo out) ------
__device__ __forceinline__ float blockReduceSum(float val)
{
    __shared__ float red[8];
    __syncthreads();
    int lane = threadIdx.x & 31, wid = threadIdx.x >> 5;
    #pragma unroll
    for (int o = 16; o > 0; o >>= 1) val += __shfl_down_sync(0xffffffffu, val, o);
    if (lane == 0) red[wid] = val;
    __syncthreads();
    if (wid == 0) {
        val = (lane < 8) ? red[lane] : 0.f;
        #pragma unroll
        for (int o = 4; o > 0; o >>= 1) val += __shfl_down_sync(0xffffffffu, val, o);
        if (lane == 0) red[0] = val;
    }
    __syncthreads();
    return red[0];
}

__global__ __launch_bounds__(256)
void add_ln_kernel(const float* __restrict__ a, const float* __restrict__ res,
                   const float* __restrict__ g, const float* __restrict__ bt,
                   float* __restrict__ out,
                   __nv_bfloat16* __restrict__ ohi, __nv_bfloat16* __restrict__ olo)
{
    const int row = blockIdx.x;
    const int tid = threadIdx.x;
    float v[3];
    float sum = 0.f;
    #pragma unroll
    for (int i = 0; i < 3; i++) {
        int c = tid + i * 256;
        v[i] = a[(size_t)row * DMODEL + c] + res[(size_t)row * DMODEL + c];
        sum += v[i];
    }
    sum = blockReduceSum(sum);
    const float mu = sum * (1.f / DMODEL);
    float s2 = 0.f;
    #pragma unroll
    for (int i = 0; i < 3; i++) { float d = v[i] - mu; s2 += d * d; }
    s2 = blockReduceSum(s2);
    const float rs = rsqrtf(s2 * (1.f / DMODEL) + 1e-12f);
    #pragma unroll
    for (int i = 0; i < 3; i++) {
        int c = tid + i * 256;
        float val = (v[i] - mu) * rs * g[c] + bt[c];
        out[(size_t)row * DMODEL + c] = val;
        if (ohi) {
            float hf = __bfloat162float(__float2bfloat16_rn(val));
            ohi[(size_t)row * DMODEL + c] = __float2bfloat16_rn(val);
            olo[(size_t)row * DMODEL + c] = __float2bfloat16_rn(val - hf);
        }
    }
}

// ---------------- driver -----------------------------------------------------
extern "C" void kernel_launch(void* const* d_in, const int* in_sizes, int n_in,
                              void* d_out, int out_size)
{
    const float* x     = (const float*)d_in[0];
    const int*   amask = (const int*)  d_in[1];
    const float* Wq    = (const float*)d_in[2];
    const float* bq    = (const float*)d_in[3];
    const float* Wk    = (const float*)d_in[4];
    const float* bk    = (const float*)d_in[5];
    const float* Wv    = (const float*)d_in[6];
    const float* bv    = (const float*)d_in[7];
    const float* Wo    = (const float*)d_in[8];
    const float* bo    = (const float*)d_in[9];
    const float* ln1g  = (const float*)d_in[10];
    const float* ln1b  = (const float*)d_in[11];
    const float* W1    = (const float*)d_in[12];
    const float* b1    = (const float*)d_in[13];
    const float* W2    = (const float*)d_in[14];
    const float* b2    = (const float*)d_in[15];
    const float* ln2g  = (const float*)d_in[16];
    const float* ln2b  = (const float*)d_in[17];
    float* out = (float*)d_out;

    float *h, *h2, *tmp;
    __nv_bfloat16 *whi, *wlo, *ahi, *alo, *chi, *clo, *fhi, *flo;
    __nv_bfloat16 *qhi, *qlo, *khi, *klo, *vhi, *vlo;
    cudaGetSymbolAddress((void**)&h,   g_h);
    cudaGetSymbolAddress((void**)&h2,  g_h2);
    cudaGetSymbolAddress((void**)&tmp, g_tmp);
    cudaGetSymbolAddress((void**)&whi, g_whi);
    cudaGetSymbolAddress((void**)&wlo, g_wlo);
    cudaGetSymbolAddress((void**)&ahi, g_ahi);
    cudaGetSymbolAddress((void**)&alo, g_alo);
    cudaGetSymbolAddress((void**)&qhi, g_qhi);
    cudaGetSymbolAddress((void**)&qlo, g_qlo);
    cudaGetSymbolAddress((void**)&khi, g_khi);
    cudaGetSymbolAddress((void**)&klo, g_klo);
    cudaGetSymbolAddress((void**)&vhi, g_vhi);
    cudaGetSymbolAddress((void**)&vlo, g_vlo);
    cudaGetSymbolAddress((void**)&chi, g_chi);
    cudaGetSymbolAddress((void**)&clo, g_clo);
    cudaGetSymbolAddress((void**)&fhi, g_fhi);
    cudaGetSymbolAddress((void**)&flo, g_flo);

    cudaFuncSetAttribute(hmma_gemm<4>, cudaFuncAttributeMaxDynamicSharedMemorySize, GEMM_SMEM4);
    cudaFuncSetAttribute(hmma_gemm<2>, cudaFuncAttributeMaxDynamicSharedMemorySize, GEMM_SMEM2);
    cudaFuncSetAttribute(attn_hmma, cudaFuncAttributeMaxDynamicSharedMemorySize, ATT_SMEM);

    const int nDD4 = SZ_DD / 4;
    const int nDF4 = SZ_DF / 4;
    f2bf<<<nDD4/256, 256>>>((const float4*)Wq, (uint2*)(whi+OQ),  (uint2*)(wlo+OQ),  nDD4);
    f2bf<<<nDD4/256, 256>>>((const float4*)Wk, (uint2*)(whi+OKk), (uint2*)(wlo+OKk), nDD4);
    f2bf<<<nDD4/256, 256>>>((const float4*)Wv, (uint2*)(whi+OV),  (uint2*)(wlo+OV),  nDD4);
    f2bf<<<nDD4/256, 256>>>((const float4*)Wo, (uint2*)(whi+OO),  (uint2*)(wlo+OO),  nDD4);
    f2bf<<<nDF4/256, 256>>>((const float4*)W1, (uint2*)(whi+O1),  (uint2*)(wlo+O1),  nDF4);
    f2bf<<<nDF4/256, 256>>>((const float4*)W2, (uint2*)(whi+O2),  (uint2*)(wlo+O2),  nDF4);

    const int nAct4 = NTOK * DMODEL / 4;
    const dim3 gQKV(DMODEL / 128, NTOK / 128, 3);   // MT=4
    const dim3 gD2 (DMODEL / 128, NTOK / 64,  1);   // MT=2: (6, 64)
    const dim3 gF  (FFD    / 128, NTOK / 128, 1);   // MT=4
    const dim3 gA(SEQ / 64, NH, BATCH);

    f2bf<<<nAct4/256, 256>>>((const float4*)x, (uint2*)ahi, (uint2*)alo, nAct4);

    for (int i = 0; i < NL; i++) {
        const float* cur = (i == 0) ? x : h;
        const size_t wdd = (size_t)i * DMODEL * DMODEL;
        const size_t wdf = (size_t)i * DMODEL * FFD;

        GemmParams pq = {};
        pq.job[0] = { whi+OQ+wdd,  wlo+OQ+wdd,  bq + i*DMODEL, 0, qhi, qlo, 0.125f, 0 };
        pq.job[1] = { whi+OKk+wdd, wlo+OKk+wdd, bk + i*DMODEL, 0, khi, klo, 1.f,    0 };
        pq.job[2] = { whi+OV+wdd,  wlo+OV+wdd,  bv + i*DMODEL, 0, vhi, vlo, 1.f,    0 };
        hmma_gemm<4><<<gQKV, 128, GEMM_SMEM4>>>(ahi, alo, pq, NTOK, DMODEL, DMODEL);

        attn_hmma<<<gA, 128, ATT_SMEM>>>(qhi, qlo, khi, klo, vhi, vlo, amask, chi, clo);

        GemmParams po = {};
        po.job[0] = { whi+OO+wdd, wlo+OO+wdd, bo + i*DMODEL, tmp, 0, 0, 1.f, 0 };
        hmma_gemm<2><<<gD2, 128, GEMM_SMEM2>>>(chi, clo, po, NTOK, DMODEL, DMODEL);

        add_ln_kernel<<<NTOK, 256>>>(tmp, cur, ln1g + i*DMODEL, ln1b + i*DMODEL,
                                     h2, ahi, alo);

        GemmParams p1 = {};
        p1.job[0] = { whi+O1+wdf, wlo+O1+wdf, b1 + i*FFD, 0, fhi, flo, 1.f, 1 };
        hmma_gemm<4><<<gF, 128, GEMM_SMEM4>>>(ahi, alo, p1, NTOK, FFD, DMODEL);

        GemmParams p2 = {};
        p2.job[0] = { whi+O2+wdf, wlo+O2+wdf, b2 + i*DMODEL, tmp, 0, 0, 1.f, 0 };
        hmma_gemm<2><<<gD2, 128, GEMM_SMEM2>>>(fhi, flo, p2, NTOK, DMODEL, FFD);

        float* dst = (i == NL - 1) ? out : h;
        add_ln_kernel<<<NTOK, 256>>>(tmp, h2, ln2g + i*DMODEL, ln2b + i*DMODEL,
                                     dst, (i < NL-1) ? ahi : 0, (i < NL-1) ? alo : 0);
    }
}